// round 15
// baseline (speedup 1.0000x reference)
#include <cuda_runtime.h>
#include <cuda_bf16.h>
#include <cstdint>

// Problem constants
#define BATCH 8
#define SEQ   1024
#define DIM   128
#define HEADS 8
#define DH    16
#define FFDIM 512
#define MROWS (BATCH*SEQ)   // 8192
#define NSPLIT 8

typedef unsigned long long u64;
typedef unsigned int u32;
typedef unsigned short u16;

// ------------------------- scratch (static only) ---------------------------
__device__ __align__(16) float g_x1  [MROWS * DIM];
__device__ __align__(16) float g_attp[NSPLIT * MROWS * DIM];
__device__ __align__(16) float g_lp  [NSPLIT * MROWS * HEADS];
// bf16 hi/lo split operands
__device__ __align__(16) __nv_bfloat16 g_qkvh[MROWS * 384], g_qkvl[MROWS * 384];
__device__ __align__(16) __nv_bfloat16 g_xh [MROWS * DIM],  g_xl [MROWS * DIM];
__device__ __align__(16) __nv_bfloat16 g_ath[MROWS * DIM],  g_atl[MROWS * DIM];
__device__ __align__(16) __nv_bfloat16 g_x1h[MROWS * DIM],  g_x1l[MROWS * DIM];
__device__ __align__(16) __nv_bfloat16 g_ffh[MROWS * FFDIM],g_ffl[MROWS * FFDIM];
// transposed + split weights: [N x K] K-major
__device__ __align__(16) __nv_bfloat16 g_WqkvTh[384 * DIM], g_WqkvTl[384 * DIM];
__device__ __align__(16) __nv_bfloat16 g_WoTh [DIM * DIM],  g_WoTl [DIM * DIM];
__device__ __align__(16) __nv_bfloat16 g_W1Th [FFDIM * DIM],g_W1Tl [FFDIM * DIM];
__device__ __align__(16) __nv_bfloat16 g_W2Th [DIM * FFDIM],g_W2Tl [DIM * FFDIM];

// ------------------------------ helpers ------------------------------------
__device__ __forceinline__ float ex2f(float x) {
    float y; asm("ex2.approx.f32 %0, %1;" : "=f"(y) : "f"(x)); return y;
}
__device__ __forceinline__ float rcpf(float x) {
    float y; asm("rcp.approx.f32 %0, %1;" : "=f"(y) : "f"(x)); return y;
}
__device__ __forceinline__ void bfsplit(float v, u16& hb, u16& lb) {
    __nv_bfloat16 h = __float2bfloat16(v);
    float rh = __bfloat162float(h);
    __nv_bfloat16 l = __float2bfloat16(v - rh);
    hb = *reinterpret_cast<u16*>(&h);
    lb = *reinterpret_cast<u16*>(&l);
}
// pack (w0 -> low 16, w1 -> high 16) bf16 hi + residual lo
__device__ __forceinline__ void pack_split2(float w0, float w1, u32& hp, u32& lp2) {
    __nv_bfloat162 hh = __floats2bfloat162_rn(w0, w1);
    float2 back = __bfloat1622float2(hh);
    __nv_bfloat162 ll = __floats2bfloat162_rn(w0 - back.x, w1 - back.y);
    hp  = *reinterpret_cast<u32*>(&hh);
    lp2 = *reinterpret_cast<u32*>(&ll);
}
// w = exp(10*tanh(dot/4 + ev) - 10), fixed-max softmax weight
__device__ __forceinline__ float expw(float dot, float ev) {
    float t = ex2f(fmaf(dot, 0.72134752f, ev * 2.8853901f));
    float u = rcpf(t + 1.0f);
    return ex2f(-28.8539008f * u);
}
// mma.sync m16n8k16 bf16 -> f32 accumulate in place
__device__ __forceinline__ void mma16816(float* c, const u32* a, const u32* b) {
    asm volatile(
        "mma.sync.aligned.m16n8k16.row.col.f32.bf16.bf16.f32 "
        "{%0,%1,%2,%3}, {%4,%5,%6,%7}, {%8,%9}, {%0,%1,%2,%3};"
        : "+f"(c[0]), "+f"(c[1]), "+f"(c[2]), "+f"(c[3])
        : "r"(a[0]), "r"(a[1]), "r"(a[2]), "r"(a[3]), "r"(b[0]), "r"(b[1]));
}
// shared-space address
__device__ __forceinline__ u32 s2u(const void* p) {
    u32 a; asm("{ .reg .u64 t; cvta.to.shared.u64 t, %1; cvt.u32.u64 %0, t; }"
               : "=r"(a) : "l"(p)); return a;
}
// ldmatrix x4
__device__ __forceinline__ void ldsm4(u32* r, u32 a) {
    asm volatile("ldmatrix.sync.aligned.m8n8.x4.shared.b16 {%0,%1,%2,%3}, [%4];"
                 : "=r"(r[0]), "=r"(r[1]), "=r"(r[2]), "=r"(r[3]) : "r"(a));
}
// ldmatrix x4 transposed (for B-fragments from row-major [k][n] tiles)
__device__ __forceinline__ void ldsm4t(u32* r, u32 a) {
    asm volatile("ldmatrix.sync.aligned.m8n8.x4.trans.shared.b16 {%0,%1,%2,%3}, [%4];"
                 : "=r"(r[0]), "=r"(r[1]), "=r"(r[2]), "=r"(r[3]) : "r"(a));
}

#define GPAD 40

// ---------------------------------------------------------------------------
// HMMA GEMM 128x64 tile, LDSM fragment loads. 256 threads, 8 warps (4x2).
// EPI: 0 fp32 | 1 relu(acc+bias)->bf16 h/l | 2 resid+alpha*acc -> fp32+h/l
//      3 resid+alpha*(acc+bias) -> fp32 | 4 plain bf16 h/l
// ---------------------------------------------------------------------------
template <int EPI>
__global__ void __launch_bounds__(256) mmagemm_k(
    const __nv_bfloat16* __restrict__ Ah, const __nv_bfloat16* __restrict__ Al, int lda,
    const __nv_bfloat16* __restrict__ BTh, const __nv_bfloat16* __restrict__ BTl,
    int K,
    float* __restrict__ C, int ldc,
    __nv_bfloat16* __restrict__ Chb, __nv_bfloat16* __restrict__ Clb, int ldcb,
    const float* __restrict__ bias,
    const float* __restrict__ resid, int ldr,
    const float* __restrict__ alphap)
{
    __shared__ __align__(16) __nv_bfloat16 sAh[128 * GPAD];
    __shared__ __align__(16) __nv_bfloat16 sAl[128 * GPAD];
    __shared__ __align__(16) __nv_bfloat16 sBh[64 * GPAD];
    __shared__ __align__(16) __nv_bfloat16 sBl[64 * GPAD];

    const int tid  = threadIdx.x;
    const int warp = tid >> 5;
    const int lane = tid & 31;
    const int grp  = lane >> 2;
    const int tig  = lane & 3;
    const int wm   = warp & 3;
    const int wn   = warp >> 2;
    const int row0 = blockIdx.y * 128;
    const int col0 = blockIdx.x * 64;

    const int a_r0 = tid >> 2;
    const int a_k  = (tid & 3) * 8;
    const int b_n  = tid >> 2;
    const int b_k  = (tid & 3) * 8;
    const int a_dst0 = a_r0 * GPAD + a_k;
    const int b_dst  = b_n * GPAD + b_k;

    const u32 sAh_u = s2u(sAh), sAl_u = s2u(sAl);
    const u32 sBh_u = s2u(sBh), sBl_u = s2u(sBl);
    const int aoff = (((lane & 15) * GPAD) + (lane >> 4) * 8) * 2;
    const int boff = ((((lane & 7) + ((lane >> 4) & 1) * 8) * GPAD) + ((lane >> 3) & 1) * 8) * 2;

    float acc[2][4][4];
#pragma unroll
    for (int mt = 0; mt < 2; mt++)
#pragma unroll
        for (int nt = 0; nt < 4; nt++)
#pragma unroll
            for (int i = 0; i < 4; i++) acc[mt][nt][i] = 0.f;

    uint4 pAh[2], pAl[2], pBh, pBl;
#pragma unroll
    for (int i = 0; i < 2; i++) {
        const size_t go = (size_t)(row0 + a_r0 + i * 64) * lda + a_k;
        pAh[i] = *(const uint4*)(Ah + go);
        pAl[i] = *(const uint4*)(Al + go);
    }
    {
        const size_t go = (size_t)(col0 + b_n) * K + b_k;
        pBh = *(const uint4*)(BTh + go);
        pBl = *(const uint4*)(BTl + go);
    }

    const int nchunks = K >> 5;
    for (int kc = 0; kc < nchunks; kc++) {
#pragma unroll
        for (int i = 0; i < 2; i++) {
            *(uint4*)&sAh[a_dst0 + i * 64 * GPAD] = pAh[i];
            *(uint4*)&sAl[a_dst0 + i * 64 * GPAD] = pAl[i];
        }
        *(uint4*)&sBh[b_dst] = pBh;
        *(uint4*)&sBl[b_dst] = pBl;
        __syncthreads();

        if (kc + 1 < nchunks) {
            const int k0 = (kc + 1) * 32;
#pragma unroll
            for (int i = 0; i < 2; i++) {
                const size_t go = (size_t)(row0 + a_r0 + i * 64) * lda + k0 + a_k;
                pAh[i] = *(const uint4*)(Ah + go);
                pAl[i] = *(const uint4*)(Al + go);
            }
            const size_t go = (size_t)(col0 + b_n) * K + k0 + b_k;
            pBh = *(const uint4*)(BTh + go);
            pBl = *(const uint4*)(BTl + go);
        }

#pragma unroll
        for (int ks = 0; ks < 32; ks += 16) {
            u32 ah[2][4], al[2][4];
#pragma unroll
            for (int mt = 0; mt < 2; mt++) {
                const int base = ((wm * 32 + mt * 16) * GPAD + ks) * 2;
                ldsm4(ah[mt], sAh_u + base + aoff);
                ldsm4(al[mt], sAl_u + base + aoff);
            }
            u32 bh[2][4], bl[2][4];
#pragma unroll
            for (int p = 0; p < 2; p++) {
                const int base = ((wn * 32 + p * 16) * GPAD + ks) * 2;
                ldsm4(bh[p], sBh_u + base + boff);
                ldsm4(bl[p], sBl_u + base + boff);
            }
#pragma unroll
            for (int mt = 0; mt < 2; mt++)
#pragma unroll
                for (int nt = 0; nt < 4; nt++) {
                    const u32* bhp = &bh[nt >> 1][(nt & 1) * 2];
                    const u32* blp = &bl[nt >> 1][(nt & 1) * 2];
                    mma16816(acc[mt][nt], ah[mt], bhp);
                    mma16816(acc[mt][nt], ah[mt], blp);
                    mma16816(acc[mt][nt], al[mt], bhp);
                }
        }
        __syncthreads();
    }

    float alpha = 0.f;
    if (EPI == 2 || EPI == 3) alpha = __ldg(alphap);

#pragma unroll
    for (int mt = 0; mt < 2; mt++) {
#pragma unroll
        for (int rh = 0; rh < 2; rh++) {
            const int r = row0 + wm * 32 + mt * 16 + grp + rh * 8;
#pragma unroll
            for (int nt = 0; nt < 4; nt++) {
                const int c = col0 + wn * 32 + nt * 8 + tig * 2;
                float v0 = acc[mt][nt][rh * 2 + 0];
                float v1 = acc[mt][nt][rh * 2 + 1];
                if (EPI == 1 || EPI == 3) {
                    float2 bb = *(const float2*)&bias[c];
                    v0 += bb.x; v1 += bb.y;
                }
                if (EPI == 1) {
                    v0 = fmaxf(v0, 0.f); v1 = fmaxf(v1, 0.f);
                }
                if (EPI == 2 || EPI == 3) {
                    float2 rv = *(const float2*)&resid[(size_t)r * ldr + c];
                    v0 = fmaf(alpha, v0, rv.x);
                    v1 = fmaf(alpha, v1, rv.y);
                }
                if (EPI == 0 || EPI == 2 || EPI == 3)
                    *(float2*)&C[(size_t)r * ldc + c] = make_float2(v0, v1);
                if (EPI == 1 || EPI == 2 || EPI == 4) {
                    u32 hp, lp2;
                    pack_split2(v0, v1, hp, lp2);
                    *(u32*)&Chb[(size_t)r * ldcb + c] = hp;
                    *(u32*)&Clb[(size_t)r * ldcb + c] = lp2;
                }
            }
        }
    }
}

// ---------------------------------------------------------------------------
// HMMA GEMM 64x64 tile (Wo, ff2), LDSM fragment loads. 128 threads, 4 warps.
// ---------------------------------------------------------------------------
template <int EPI>
__global__ void __launch_bounds__(128) mmagemm64_k(
    const __nv_bfloat16* __restrict__ Ah, const __nv_bfloat16* __restrict__ Al, int lda,
    const __nv_bfloat16* __restrict__ BTh, const __nv_bfloat16* __restrict__ BTl,
    int K,
    float* __restrict__ C, int ldc,
    __nv_bfloat16* __restrict__ Chb, __nv_bfloat16* __restrict__ Clb, int ldcb,
    const float* __restrict__ bias,
    const float* __restrict__ resid, int ldr,
    const float* __restrict__ alphap)
{
    __shared__ __align__(16) __nv_bfloat16 sAh[64 * GPAD];
    __shared__ __align__(16) __nv_bfloat16 sAl[64 * GPAD];
    __shared__ __align__(16) __nv_bfloat16 sBh[64 * GPAD];
    __shared__ __align__(16) __nv_bfloat16 sBl[64 * GPAD];

    const int tid  = threadIdx.x;
    const int warp = tid >> 5;
    const int lane = tid & 31;
    const int grp  = lane >> 2;
    const int tig  = lane & 3;
    const int wm   = warp & 1;
    const int wn   = warp >> 1;
    const int row0 = blockIdx.y * 64;
    const int col0 = blockIdx.x * 64;

    const int a_r0 = tid >> 2;
    const int a_k  = (tid & 3) * 8;
    const int a_dst0 = a_r0 * GPAD + a_k;

    const u32 sAh_u = s2u(sAh), sAl_u = s2u(sAl);
    const u32 sBh_u = s2u(sBh), sBl_u = s2u(sBl);
    const int aoff = (((lane & 15) * GPAD) + (lane >> 4) * 8) * 2;
    const int boff = ((((lane & 7) + ((lane >> 4) & 1) * 8) * GPAD) + ((lane >> 3) & 1) * 8) * 2;

    float acc[2][4][4];
#pragma unroll
    for (int mt = 0; mt < 2; mt++)
#pragma unroll
        for (int nt = 0; nt < 4; nt++)
#pragma unroll
            for (int i = 0; i < 4; i++) acc[mt][nt][i] = 0.f;

    uint4 pAh[2], pAl[2], pBh[2], pBl[2];
#pragma unroll
    for (int i = 0; i < 2; i++) {
        const size_t ga = (size_t)(row0 + a_r0 + i * 32) * lda + a_k;
        pAh[i] = *(const uint4*)(Ah + ga);
        pAl[i] = *(const uint4*)(Al + ga);
        const size_t gb = (size_t)(col0 + a_r0 + i * 32) * K + a_k;
        pBh[i] = *(const uint4*)(BTh + gb);
        pBl[i] = *(const uint4*)(BTl + gb);
    }

    const int nchunks = K >> 5;
    for (int kc = 0; kc < nchunks; kc++) {
#pragma unroll
        for (int i = 0; i < 2; i++) {
            *(uint4*)&sAh[a_dst0 + i * 32 * GPAD] = pAh[i];
            *(uint4*)&sAl[a_dst0 + i * 32 * GPAD] = pAl[i];
            *(uint4*)&sBh[a_dst0 + i * 32 * GPAD] = pBh[i];
            *(uint4*)&sBl[a_dst0 + i * 32 * GPAD] = pBl[i];
        }
        __syncthreads();

        if (kc + 1 < nchunks) {
            const int k0 = (kc + 1) * 32;
#pragma unroll
            for (int i = 0; i < 2; i++) {
                const size_t ga = (size_t)(row0 + a_r0 + i * 32) * lda + k0 + a_k;
                pAh[i] = *(const uint4*)(Ah + ga);
                pAl[i] = *(const uint4*)(Al + ga);
                const size_t gb = (size_t)(col0 + a_r0 + i * 32) * K + k0 + a_k;
                pBh[i] = *(const uint4*)(BTh + gb);
                pBl[i] = *(const uint4*)(BTl + gb);
            }
        }

#pragma unroll
        for (int ks = 0; ks < 32; ks += 16) {
            u32 ah[2][4], al[2][4];
#pragma unroll
            for (int mt = 0; mt < 2; mt++) {
                const int base = ((wm * 32 + mt * 16) * GPAD + ks) * 2;
                ldsm4(ah[mt], sAh_u + base + aoff);
                ldsm4(al[mt], sAl_u + base + aoff);
            }
            u32 bh[2][4], bl[2][4];
#pragma unroll
            for (int p = 0; p < 2; p++) {
                const int base = ((wn * 32 + p * 16) * GPAD + ks) * 2;
                ldsm4(bh[p], sBh_u + base + boff);
                ldsm4(bl[p], sBl_u + base + boff);
            }
#pragma unroll
            for (int mt = 0; mt < 2; mt++)
#pragma unroll
                for (int nt = 0; nt < 4; nt++) {
                    const u32* bhp = &bh[nt >> 1][(nt & 1) * 2];
                    const u32* blp = &bl[nt >> 1][(nt & 1) * 2];
                    mma16816(acc[mt][nt], ah[mt], bhp);
                    mma16816(acc[mt][nt], ah[mt], blp);
                    mma16816(acc[mt][nt], al[mt], bhp);
                }
        }
        __syncthreads();
    }

    float alpha = 0.f;
    if (EPI == 2 || EPI == 3) alpha = __ldg(alphap);

#pragma unroll
    for (int mt = 0; mt < 2; mt++) {
#pragma unroll
        for (int rh = 0; rh < 2; rh++) {
            const int r = row0 + wm * 32 + mt * 16 + grp + rh * 8;
#pragma unroll
            for (int nt = 0; nt < 4; nt++) {
                const int c = col0 + wn * 32 + nt * 8 + tig * 2;
                float v0 = acc[mt][nt][rh * 2 + 0];
                float v1 = acc[mt][nt][rh * 2 + 1];
                if (EPI == 1 || EPI == 3) {
                    float2 bb = *(const float2*)&bias[c];
                    v0 += bb.x; v1 += bb.y;
                }
                if (EPI == 1) {
                    v0 = fmaxf(v0, 0.f); v1 = fmaxf(v1, 0.f);
                }
                if (EPI == 2 || EPI == 3) {
                    float2 rv = *(const float2*)&resid[(size_t)r * ldr + c];
                    v0 = fmaf(alpha, v0, rv.x);
                    v1 = fmaf(alpha, v1, rv.y);
                }
                if (EPI == 0 || EPI == 2 || EPI == 3)
                    *(float2*)&C[(size_t)r * ldc + c] = make_float2(v0, v1);
                if (EPI == 1 || EPI == 2 || EPI == 4) {
                    u32 hp, lp2;
                    pack_split2(v0, v1, hp, lp2);
                    *(u32*)&Chb[(size_t)r * ldcb + c] = hp;
                    *(u32*)&Clb[(size_t)r * ldcb + c] = lp2;
                }
            }
        }
    }
}

// ---------------------------------------------------------------------------
// Prep: split x (elementwise)
// ---------------------------------------------------------------------------
__global__ void __launch_bounds__(256) split_x_k(
    const float* __restrict__ x, __nv_bfloat16* __restrict__ xh,
    __nv_bfloat16* __restrict__ xl, int n4)
{
    int i = blockIdx.x * 256 + threadIdx.x;
    if (i >= n4) return;
    float4 vv = ((const float4*)x)[i];
    float a[4] = { vv.x, vv.y, vv.z, vv.w };
    u16 hb[4], lb[4];
#pragma unroll
    for (int j = 0; j < 4; j++) bfsplit(a[j], hb[j], lb[j]);
    ((uint2*)xh)[i] = make_uint2((u32)hb[0] | ((u32)hb[1] << 16), (u32)hb[2] | ((u32)hb[3] << 16));
    ((uint2*)xl)[i] = make_uint2((u32)lb[0] | ((u32)lb[1] << 16), (u32)lb[2] | ((u32)lb[3] << 16));
}

// ---------------------------------------------------------------------------
// Prep: ALL weight transposes+splits, 192 blocks (round-8 verified).
// ---------------------------------------------------------------------------
__global__ void __launch_bounds__(256) wsplit_all_k(
    const float* __restrict__ Wq, const float* __restrict__ Wk,
    const float* __restrict__ Wv, const float* __restrict__ Wo,
    const float* __restrict__ W1, const float* __restrict__ W2,
    __nv_bfloat16* __restrict__ WqkvTh, __nv_bfloat16* __restrict__ WqkvTl,
    __nv_bfloat16* __restrict__ WoTh,   __nv_bfloat16* __restrict__ WoTl,
    __nv_bfloat16* __restrict__ W1Th,   __nv_bfloat16* __restrict__ W1Tl,
    __nv_bfloat16* __restrict__ W2Th,   __nv_bfloat16* __restrict__ W2Tl)
{
    __shared__ float sT[32][33];
    const int bid = blockIdx.x;
    const float* src;
    __nv_bfloat16 *dh, *dl;
    int N, k0, n0, ldo;
    if (bid < 48) {
        int widx = bid >> 4;
        int t = bid & 15;
        src = (widx == 0) ? Wq : (widx == 1) ? Wk : Wv;
        N = 128; k0 = (t >> 2) * 32; n0 = (t & 3) * 32; ldo = 128;
        dh = WqkvTh + widx * 128 * 128;
        dl = WqkvTl + widx * 128 * 128;
    } else if (bid < 64) {
        int t = bid - 48;
        src = Wo; N = 128; k0 = (t >> 2) * 32; n0 = (t & 3) * 32; ldo = 128;
        dh = WoTh; dl = WoTl;
    } else if (bid < 128) {
        int t = bid - 64;
        src = W1; N = 512; k0 = (t & 3) * 32; n0 = (t >> 2) * 32; ldo = 128;
        dh = W1Th; dl = W1Tl;
    } else {
        int t = bid - 128;
        src = W2; N = 128; k0 = (t >> 2) * 32; n0 = (t & 3) * 32; ldo = 512;
        dh = W2Th; dl = W2Tl;
    }

    const int r = threadIdx.x >> 5, c = threadIdx.x & 31;
#pragma unroll
    for (int i = 0; i < 4; i++)
        sT[r + 8 * i][c] = src[(size_t)(k0 + r + 8 * i) * N + n0 + c];
    __syncthreads();

#pragma unroll
    for (int i = 0; i < 2; i++) {
        int idx = threadIdx.x + i * 256;
        int orow = idx >> 4;
        int oc = (idx & 15) * 2;
        u32 hp, lp2;
        pack_split2(sT[oc][orow], sT[oc + 1][orow], hp, lp2);
        size_t o = (size_t)(n0 + orow) * ldo + k0 + oc;
        *(u32*)&dh[o] = hp;
        *(u32*)&dl[o] = lp2;
    }
}

// ---------------------------------------------------------------------------
// Flash attention on HMMA, key-splits (NSPLIT=8 for wave balance).
// V staged row-major [key][dh] (uint4, like K) and fragments loaded with
// ldmatrix.x4.trans — removes the scalar transpose stores.
// __launch_bounds__(256, 4) keeps 4 blocks/SM resident.
// ---------------------------------------------------------------------------
#define KSTR 24
#define ESTR 72

__global__ void __launch_bounds__(256, 4) attn_mma_k(
    const __nv_bfloat16* __restrict__ qkvh, const __nv_bfloat16* __restrict__ qkvl,
    const float* __restrict__ e,
    float* __restrict__ attp, float* __restrict__ lp)
{
    __shared__ __align__(16) __nv_bfloat16 sKh[64 * KSTR], sKl[64 * KSTR];
    __shared__ __align__(16) __nv_bfloat16 sVh[64 * KSTR], sVl[64 * KSTR];
    __shared__ __align__(16) float es[128 * ESTR];     // 36 KB

    const int qt = blockIdx.x;
    const int h  = blockIdx.y;
    const int bz = blockIdx.z;
    const int b = bz >> 3, split = bz & 7;
    const int tid = threadIdx.x;
    const int w = tid >> 5, lane = tid & 31;
    const int grp = lane >> 2, tig = lane & 3;

    const int qrow = qt * 128 + w * 16 + grp;
    const size_t grow = (size_t)b * SEQ + qrow;

    u32 qfh[4], qfl[4];
    {
        const size_t b0 = grow * 384 + h * DH;
        const size_t b8 = (grow + 8) * 384 + h * DH;
        qfh[0] = *(const u32*)&qkvh[b0 + tig * 2];
        qfh[1] = *(const u32*)&qkvh[b8 + tig * 2];
        qfh[2] = *(const u32*)&qkvh[b0 + tig * 2 + 8];
        qfh[3] = *(const u32*)&qkvh[b8 + tig * 2 + 8];
        qfl[0] = *(const u32*)&qkvl[b0 + tig * 2];
        qfl[1] = *(const u32*)&qkvl[b8 + tig * 2];
        qfl[2] = *(const u32*)&qkvl[b0 + tig * 2 + 8];
        qfl[3] = *(const u32*)&qkvl[b8 + tig * 2 + 8];
    }

    float o0[4] = {0.f, 0.f, 0.f, 0.f};
    float o1[4] = {0.f, 0.f, 0.f, 0.f};
    float la = 0.f, lb = 0.f;

    // K/V staging ids (both uint4, V row-major like K)
    const int skey = tid & 63;
    const int ssel = (tid >> 6) & 1;
    const int shl  = tid >> 7;
    const __nv_bfloat16* ssrc = shl ? qkvl : qkvh;
    __nv_bfloat16* kdst = shl ? sKl : sKh;
    __nv_bfloat16* vdst = shl ? sVl : sVh;
    const int kvdsto = skey * KSTR + ssel * 8;

    // e staging ids (coalesced)
    const int e_row = tid >> 4;
    const int e_c16 = (tid & 15) * 4;
    const float* ebase = e + ((size_t)b * SEQ + qt * 128) * SEQ;

    const int er0 = (w * 16 + grp) * ESTR + tig * 2;
    const int er8 = er0 + 8 * ESTR;

    // LDSM per-lane offsets (bytes)
    const u32 sKh_u = s2u(sKh), sKl_u = s2u(sKl);
    const u32 sVh_u = s2u(sVh), sVl_u = s2u(sVl);
    // K: B-style (row = key within n8 pair, col = k-halves)
    const int kfoff = ((((lane & 7) + ((lane >> 4) & 1) * 8) * KSTR) + ((lane >> 3) & 1) * 8) * 2;
    // V trans: A-style addressing (rows = 16 keys, col-halves = dh 0-7 / 8-15)
    const int vfoff = (((lane & 15) * KSTR) + (lane >> 4) * 8) * 2;

    const int kstart = split * (SEQ / NSPLIT);   // 128 keys per split

    for (int jc = 0; jc < (SEQ / NSPLIT) / 64; jc++) {   // 2 chunks
        const int k0 = kstart + jc * 64;
        __syncthreads();
        {
            const size_t g = ((size_t)b * SEQ + k0 + skey) * 384 + 128 + h * DH + ssel * 8;
            *(uint4*)&kdst[kvdsto] = *(const uint4*)&ssrc[g];
            *(uint4*)&vdst[kvdsto] = *(const uint4*)&ssrc[g + 128];
        }
#pragma unroll
        for (int i = 0; i < 8; i++) {
            int row = e_row + i * 16;
            uint4 ev = *(const uint4*)&ebase[(size_t)row * SEQ + k0 + e_c16];
            *(uint4*)&es[row * ESTR + e_c16] = ev;
        }
        __syncthreads();

        u32 ph0[8], ph8[8], pl0[8], pl8[8];
#pragma unroll
        for (int p = 0; p < 4; p++) {       // covers nt = 2p, 2p+1
            u32 kh[4], kl[4];
            ldsm4(kh, sKh_u + p * 16 * KSTR * 2 + kfoff);
            ldsm4(kl, sKl_u + p * 16 * KSTR * 2 + kfoff);
#pragma unroll
            for (int q = 0; q < 2; q++) {
                const int nt = 2 * p + q;
                float c[4] = {0.f, 0.f, 0.f, 0.f};
                mma16816(c, qfh, &kh[q * 2]);
                mma16816(c, qfh, &kl[q * 2]);
                mma16816(c, qfl, &kh[q * 2]);

                float2 e0 = *(const float2*)&es[er0 + nt * 8];
                float2 e8 = *(const float2*)&es[er8 + nt * 8];
                float w00 = expw(c[0], e0.x);
                float w01 = expw(c[1], e0.y);
                float w10 = expw(c[2], e8.x);
                float w11 = expw(c[3], e8.y);
                la += w00 + w01;
                lb += w10 + w11;
                pack_split2(w00, w01, ph0[nt], pl0[nt]);
                pack_split2(w10, w11, ph8[nt], pl8[nt]);
            }
        }

#pragma unroll
        for (int kc = 0; kc < 4; kc++) {
            u32 ah[4] = { ph0[2 * kc], ph8[2 * kc], ph0[2 * kc + 1], ph8[2 * kc + 1] };
            u32 al[4] = { pl0[2 * kc], pl8[2 * kc], pl0[2 * kc + 1], pl8[2 * kc + 1] };
            u32 vh[4], vl[4];   // trans: {n0k0-7, n0k8-15, n1k0-7, n1k8-15}
            ldsm4t(vh, sVh_u + kc * 16 * KSTR * 2 + vfoff);
            ldsm4t(vl, sVl_u + kc * 16 * KSTR * 2 + vfoff);
            mma16816(o0, ah, &vh[0]);
            mma16816(o1, ah, &vh[2]);
            mma16816(o0, al, &vh[0]);
            mma16816(o1, al, &vh[2]);
            mma16816(o0, ah, &vl[0]);
            mma16816(o1, ah, &vl[2]);
        }
    }

    la += __shfl_xor_sync(0xffffffffu, la, 1);
    la += __shfl_xor_sync(0xffffffffu, la, 2);
    lb += __shfl_xor_sync(0xffffffffu, lb, 1);
    lb += __shfl_xor_sync(0xffffffffu, lb, 2);

    float* opa = attp + ((size_t)split * MROWS + grow) * DIM + h * DH;
    float* opb = attp + ((size_t)split * MROWS + grow + 8) * DIM + h * DH;
    *(float2*)&opa[tig * 2]     = make_float2(o0[0], o0[1]);
    *(float2*)&opa[8 + tig * 2] = make_float2(o1[0], o1[1]);
    *(float2*)&opb[tig * 2]     = make_float2(o0[2], o0[3]);
    *(float2*)&opb[8 + tig * 2] = make_float2(o1[2], o1[3]);
    if (tig == 0) {
        lp[((size_t)split * MROWS + grow) * HEADS + h]     = la;
        lp[((size_t)split * MROWS + grow + 8) * HEADS + h] = lb;
    }
}

// ---------------------------------------------------------------------------
// Combine split partials -> normalized att as bf16 hi/lo (1024 blocks).
// ---------------------------------------------------------------------------
__global__ void __launch_bounds__(256) combine_k(
    const float* __restrict__ attp, const float* __restrict__ lp,
    __nv_bfloat16* __restrict__ ath, __nv_bfloat16* __restrict__ atl)
{
    int idx = blockIdx.x * 256 + threadIdx.x;
    int row = idx >> 5;
    int c4  = idx & 31;
    int h   = c4 >> 2;
    float4 s = make_float4(0.f, 0.f, 0.f, 0.f);
    float l = 0.f;
#pragma unroll
    for (int sp = 0; sp < NSPLIT; sp++) {
        float4 vv = *(const float4*)&attp[((size_t)sp * MROWS + row) * DIM + c4 * 4];
        s.x += vv.x; s.y += vv.y; s.z += vv.z; s.w += vv.w;
        l += lp[((size_t)sp * MROWS + row) * HEADS + h];
    }
    float inv = 1.0f / l;
    u32 hp, lp2;
    pack_split2(s.x * inv, s.y * inv, hp, lp2);
    *(u32*)&ath[(size_t)row * DIM + c4 * 4]     = hp;
    *(u32*)&atl[(size_t)row * DIM + c4 * 4]     = lp2;
    pack_split2(s.z * inv, s.w * inv, hp, lp2);
    *(u32*)&ath[(size_t)row * DIM + c4 * 4 + 2] = hp;
    *(u32*)&atl[(size_t)row * DIM + c4 * 4 + 2] = lp2;
}

// ---------------------------------------------------------------------------
// Launch
// ---------------------------------------------------------------------------
extern "C" void kernel_launch(void* const* d_in, const int* in_sizes, int n_in,
                              void* d_out, int out_size)
{
    const float* x  = (const float*)d_in[0];
    const float* e  = (const float*)d_in[1];
    const float* Wq = (const float*)d_in[2];
    const float* Wk = (const float*)d_in[3];
    const float* Wv = (const float*)d_in[4];
    const float* Wo = (const float*)d_in[5];
    const float* W1 = (const float*)d_in[6];
    const float* b1 = (const float*)d_in[7];
    const float* W2 = (const float*)d_in[8];
    const float* b2 = (const float*)d_in[9];
    const float* alpha1 = (const float*)d_in[10];
    const float* alpha2 = (const float*)d_in[11];
    float* out = (float*)d_out;

    float *x1, *attp, *lpv;
    __nv_bfloat16 *qkvh, *qkvl, *xh, *xl, *ath, *atl, *x1h, *x1l, *ffh, *ffl;
    __nv_bfloat16 *WqkvTh, *WqkvTl, *WoTh, *WoTl, *W1Th, *W1Tl, *W2Th, *W2Tl;
    cudaGetSymbolAddress((void**)&x1,   g_x1);
    cudaGetSymbolAddress((void**)&attp, g_attp);
    cudaGetSymbolAddress((void**)&lpv,  g_lp);
    cudaGetSymbolAddress((void**)&qkvh, g_qkvh);
    cudaGetSymbolAddress((void**)&qkvl, g_qkvl);
    cudaGetSymbolAddress((void**)&xh,   g_xh);
    cudaGetSymbolAddress((void**)&xl,   g_xl);
    cudaGetSymbolAddress((void**)&ath,  g_ath);
    cudaGetSymbolAddress((void**)&atl,  g_atl);
    cudaGetSymbolAddress((void**)&x1h,  g_x1h);
    cudaGetSymbolAddress((void**)&x1l,  g_x1l);
    cudaGetSymbolAddress((void**)&ffh,  g_ffh);
    cudaGetSymbolAddress((void**)&ffl,  g_ffl);
    cudaGetSymbolAddress((void**)&WqkvTh, g_WqkvTh);
    cudaGetSymbolAddress((void**)&WqkvTl, g_WqkvTl);
    cudaGetSymbolAddress((void**)&WoTh, g_WoTh);
    cudaGetSymbolAddress((void**)&WoTl, g_WoTl);
    cudaGetSymbolAddress((void**)&W1Th, g_W1Th);
    cudaGetSymbolAddress((void**)&W1Tl, g_W1Tl);
    cudaGetSymbolAddress((void**)&W2Th, g_W2Th);
    cudaGetSymbolAddress((void**)&W2Tl, g_W2Tl);

    // preps (2 launches)
    split_x_k<<<(MROWS * DIM / 4 + 255) / 256, 256>>>(x, xh, xl, MROWS * DIM / 4);
    wsplit_all_k<<<192, 256>>>(Wq, Wk, Wv, Wo, W1, W2,
                               WqkvTh, WqkvTl, WoTh, WoTl,
                               W1Th, W1Tl, W2Th, W2Tl);

    // qkv = x @ [Wq|Wk|Wv] -> bf16 hi/lo (ldcb=384); grid 384 blocks
    mmagemm_k<4><<<dim3(384 / 64, MROWS / 128), 256>>>(
        xh, xl, DIM, WqkvTh, WqkvTl, DIM,
        nullptr, 0, qkvh, qkvl, 384, nullptr, nullptr, 0, nullptr);

    // flash attention with 8-way key splits (4096 blocks; ~6.9 waves)
    attn_mma_k<<<dim3(SEQ / 128, HEADS, BATCH * NSPLIT), 256>>>(qkvh, qkvl, e, attp, lpv);
    combine_k<<<(MROWS * DIM / 4) / 256, 256>>>(attp, lpv, ath, atl);

    // x1 = x + a1*(att @ Wo): 64x64 tiles, grid 256 blocks
    mmagemm64_k<2><<<dim3(DIM / 64, MROWS / 64), 128>>>(
        ath, atl, DIM, WoTh, WoTl, DIM,
        x1, DIM, x1h, x1l, DIM, nullptr, x, DIM, alpha1);

    // ff = relu(x1 @ W1 + b1): grid 512 blocks
    mmagemm_k<1><<<dim3(FFDIM / 64, MROWS / 128), 256>>>(
        x1h, x1l, DIM, W1Th, W1Tl, DIM,
        nullptr, 0, ffh, ffl, FFDIM, b1, nullptr, 0, nullptr);

    // out = x1 + a2*(ff @ W2 + b2): 64x64 tiles, grid 256 blocks
    mmagemm64_k<3><<<dim3(DIM / 64, MROWS / 64), 128>>>(
        ffh, ffl, FFDIM, W2Th, W2Tl, FFDIM,
        out, DIM, nullptr, nullptr, 0, b2, x1, DIM, alpha2);
}

// round 16
// speedup vs baseline: 1.0667x; 1.0667x over previous
#include <cuda_runtime.h>
#include <cuda_bf16.h>
#include <cstdint>

// Problem constants
#define BATCH 8
#define SEQ   1024
#define DIM   128
#define HEADS 8
#define DH    16
#define FFDIM 512
#define MROWS (BATCH*SEQ)   // 8192
#define NSPLIT 4

typedef unsigned long long u64;
typedef unsigned int u32;
typedef unsigned short u16;

// ------------------------- scratch (static only) ---------------------------
__device__ __align__(16) float g_x1  [MROWS * DIM];
__device__ __align__(16) float g_attp[NSPLIT * MROWS * DIM];
__device__ __align__(16) float g_lp  [NSPLIT * MROWS * HEADS];
// bf16 hi/lo split operands
__device__ __align__(16) __nv_bfloat16 g_qkvh[MROWS * 384], g_qkvl[MROWS * 384];
__device__ __align__(16) __nv_bfloat16 g_xh [MROWS * DIM],  g_xl [MROWS * DIM];
__device__ __align__(16) __nv_bfloat16 g_ath[MROWS * DIM],  g_atl[MROWS * DIM];
__device__ __align__(16) __nv_bfloat16 g_x1h[MROWS * DIM],  g_x1l[MROWS * DIM];
__device__ __align__(16) __nv_bfloat16 g_ffh[MROWS * FFDIM],g_ffl[MROWS * FFDIM];
// transposed + split weights: [N x K] K-major
__device__ __align__(16) __nv_bfloat16 g_WqkvTh[384 * DIM], g_WqkvTl[384 * DIM];
__device__ __align__(16) __nv_bfloat16 g_WoTh [DIM * DIM],  g_WoTl [DIM * DIM];
__device__ __align__(16) __nv_bfloat16 g_W1Th [FFDIM * DIM],g_W1Tl [FFDIM * DIM];
__device__ __align__(16) __nv_bfloat16 g_W2Th [DIM * FFDIM],g_W2Tl [DIM * FFDIM];

// ------------------------------ helpers ------------------------------------
__device__ __forceinline__ float ex2f(float x) {
    float y; asm("ex2.approx.f32 %0, %1;" : "=f"(y) : "f"(x)); return y;
}
__device__ __forceinline__ float rcpf(float x) {
    float y; asm("rcp.approx.f32 %0, %1;" : "=f"(y) : "f"(x)); return y;
}
__device__ __forceinline__ void bfsplit(float v, u16& hb, u16& lb) {
    __nv_bfloat16 h = __float2bfloat16(v);
    float rh = __bfloat162float(h);
    __nv_bfloat16 l = __float2bfloat16(v - rh);
    hb = *reinterpret_cast<u16*>(&h);
    lb = *reinterpret_cast<u16*>(&l);
}
// pack (w0 -> low 16, w1 -> high 16) bf16 hi + residual lo
__device__ __forceinline__ void pack_split2(float w0, float w1, u32& hp, u32& lp2) {
    __nv_bfloat162 hh = __floats2bfloat162_rn(w0, w1);
    float2 back = __bfloat1622float2(hh);
    __nv_bfloat162 ll = __floats2bfloat162_rn(w0 - back.x, w1 - back.y);
    hp  = *reinterpret_cast<u32*>(&hh);
    lp2 = *reinterpret_cast<u32*>(&ll);
}
// w = exp(10*tanh(dot/4 + ev) - 10), fixed-max softmax weight
__device__ __forceinline__ float expw(float dot, float ev) {
    float t = ex2f(fmaf(dot, 0.72134752f, ev * 2.8853901f));
    float u = rcpf(t + 1.0f);
    return ex2f(-28.8539008f * u);
}
// mma.sync m16n8k16 bf16 -> f32 accumulate in place
__device__ __forceinline__ void mma16816(float* c, const u32* a, const u32* b) {
    asm volatile(
        "mma.sync.aligned.m16n8k16.row.col.f32.bf16.bf16.f32 "
        "{%0,%1,%2,%3}, {%4,%5,%6,%7}, {%8,%9}, {%0,%1,%2,%3};"
        : "+f"(c[0]), "+f"(c[1]), "+f"(c[2]), "+f"(c[3])
        : "r"(a[0]), "r"(a[1]), "r"(a[2]), "r"(a[3]), "r"(b[0]), "r"(b[1]));
}
// shared-space address
__device__ __forceinline__ u32 s2u(const void* p) {
    u32 a; asm("{ .reg .u64 t; cvta.to.shared.u64 t, %1; cvt.u32.u64 %0, t; }"
               : "=r"(a) : "l"(p)); return a;
}
// ldmatrix x4
__device__ __forceinline__ void ldsm4(u32* r, u32 a) {
    asm volatile("ldmatrix.sync.aligned.m8n8.x4.shared.b16 {%0,%1,%2,%3}, [%4];"
                 : "=r"(r[0]), "=r"(r[1]), "=r"(r[2]), "=r"(r[3]) : "r"(a));
}
// ldmatrix x4 transposed (for B-fragments from row-major [k][n] tiles)
__device__ __forceinline__ void ldsm4t(u32* r, u32 a) {
    asm volatile("ldmatrix.sync.aligned.m8n8.x4.trans.shared.b16 {%0,%1,%2,%3}, [%4];"
                 : "=r"(r[0]), "=r"(r[1]), "=r"(r[2]), "=r"(r[3]) : "r"(a));
}

#define GPAD 40

// ---------------------------------------------------------------------------
// HMMA GEMM 128x64 tile, LDSM fragment loads. 256 threads, 8 warps (4x2).
// EPI: 0 fp32 | 1 relu(acc+bias)->bf16 h/l | 2 resid+alpha*acc -> fp32+h/l
//      3 resid+alpha*(acc+bias) -> fp32 | 4 plain bf16 h/l
// ---------------------------------------------------------------------------
template <int EPI>
__global__ void __launch_bounds__(256) mmagemm_k(
    const __nv_bfloat16* __restrict__ Ah, const __nv_bfloat16* __restrict__ Al, int lda,
    const __nv_bfloat16* __restrict__ BTh, const __nv_bfloat16* __restrict__ BTl,
    int K,
    float* __restrict__ C, int ldc,
    __nv_bfloat16* __restrict__ Chb, __nv_bfloat16* __restrict__ Clb, int ldcb,
    const float* __restrict__ bias,
    const float* __restrict__ resid, int ldr,
    const float* __restrict__ alphap)
{
    __shared__ __align__(16) __nv_bfloat16 sAh[128 * GPAD];
    __shared__ __align__(16) __nv_bfloat16 sAl[128 * GPAD];
    __shared__ __align__(16) __nv_bfloat16 sBh[64 * GPAD];
    __shared__ __align__(16) __nv_bfloat16 sBl[64 * GPAD];

    const int tid  = threadIdx.x;
    const int warp = tid >> 5;
    const int lane = tid & 31;
    const int grp  = lane >> 2;
    const int tig  = lane & 3;
    const int wm   = warp & 3;
    const int wn   = warp >> 2;
    const int row0 = blockIdx.y * 128;
    const int col0 = blockIdx.x * 64;

    const int a_r0 = tid >> 2;
    const int a_k  = (tid & 3) * 8;
    const int b_n  = tid >> 2;
    const int b_k  = (tid & 3) * 8;
    const int a_dst0 = a_r0 * GPAD + a_k;
    const int b_dst  = b_n * GPAD + b_k;

    const u32 sAh_u = s2u(sAh), sAl_u = s2u(sAl);
    const u32 sBh_u = s2u(sBh), sBl_u = s2u(sBl);
    const int aoff = (((lane & 15) * GPAD) + (lane >> 4) * 8) * 2;
    const int boff = ((((lane & 7) + ((lane >> 4) & 1) * 8) * GPAD) + ((lane >> 3) & 1) * 8) * 2;

    float acc[2][4][4];
#pragma unroll
    for (int mt = 0; mt < 2; mt++)
#pragma unroll
        for (int nt = 0; nt < 4; nt++)
#pragma unroll
            for (int i = 0; i < 4; i++) acc[mt][nt][i] = 0.f;

    uint4 pAh[2], pAl[2], pBh, pBl;
#pragma unroll
    for (int i = 0; i < 2; i++) {
        const size_t go = (size_t)(row0 + a_r0 + i * 64) * lda + a_k;
        pAh[i] = *(const uint4*)(Ah + go);
        pAl[i] = *(const uint4*)(Al + go);
    }
    {
        const size_t go = (size_t)(col0 + b_n) * K + b_k;
        pBh = *(const uint4*)(BTh + go);
        pBl = *(const uint4*)(BTl + go);
    }

    const int nchunks = K >> 5;
    for (int kc = 0; kc < nchunks; kc++) {
#pragma unroll
        for (int i = 0; i < 2; i++) {
            *(uint4*)&sAh[a_dst0 + i * 64 * GPAD] = pAh[i];
            *(uint4*)&sAl[a_dst0 + i * 64 * GPAD] = pAl[i];
        }
        *(uint4*)&sBh[b_dst] = pBh;
        *(uint4*)&sBl[b_dst] = pBl;
        __syncthreads();

        if (kc + 1 < nchunks) {
            const int k0 = (kc + 1) * 32;
#pragma unroll
            for (int i = 0; i < 2; i++) {
                const size_t go = (size_t)(row0 + a_r0 + i * 64) * lda + k0 + a_k;
                pAh[i] = *(const uint4*)(Ah + go);
                pAl[i] = *(const uint4*)(Al + go);
            }
            const size_t go = (size_t)(col0 + b_n) * K + k0 + b_k;
            pBh = *(const uint4*)(BTh + go);
            pBl = *(const uint4*)(BTl + go);
        }

#pragma unroll
        for (int ks = 0; ks < 32; ks += 16) {
            u32 ah[2][4], al[2][4];
#pragma unroll
            for (int mt = 0; mt < 2; mt++) {
                const int base = ((wm * 32 + mt * 16) * GPAD + ks) * 2;
                ldsm4(ah[mt], sAh_u + base + aoff);
                ldsm4(al[mt], sAl_u + base + aoff);
            }
            u32 bh[2][4], bl[2][4];
#pragma unroll
            for (int p = 0; p < 2; p++) {
                const int base = ((wn * 32 + p * 16) * GPAD + ks) * 2;
                ldsm4(bh[p], sBh_u + base + boff);
                ldsm4(bl[p], sBl_u + base + boff);
            }
#pragma unroll
            for (int mt = 0; mt < 2; mt++)
#pragma unroll
                for (int nt = 0; nt < 4; nt++) {
                    const u32* bhp = &bh[nt >> 1][(nt & 1) * 2];
                    const u32* blp = &bl[nt >> 1][(nt & 1) * 2];
                    mma16816(acc[mt][nt], ah[mt], bhp);
                    mma16816(acc[mt][nt], ah[mt], blp);
                    mma16816(acc[mt][nt], al[mt], bhp);
                }
        }
        __syncthreads();
    }

    float alpha = 0.f;
    if (EPI == 2 || EPI == 3) alpha = __ldg(alphap);

#pragma unroll
    for (int mt = 0; mt < 2; mt++) {
#pragma unroll
        for (int rh = 0; rh < 2; rh++) {
            const int r = row0 + wm * 32 + mt * 16 + grp + rh * 8;
#pragma unroll
            for (int nt = 0; nt < 4; nt++) {
                const int c = col0 + wn * 32 + nt * 8 + tig * 2;
                float v0 = acc[mt][nt][rh * 2 + 0];
                float v1 = acc[mt][nt][rh * 2 + 1];
                if (EPI == 1 || EPI == 3) {
                    float2 bb = *(const float2*)&bias[c];
                    v0 += bb.x; v1 += bb.y;
                }
                if (EPI == 1) {
                    v0 = fmaxf(v0, 0.f); v1 = fmaxf(v1, 0.f);
                }
                if (EPI == 2 || EPI == 3) {
                    float2 rv = *(const float2*)&resid[(size_t)r * ldr + c];
                    v0 = fmaf(alpha, v0, rv.x);
                    v1 = fmaf(alpha, v1, rv.y);
                }
                if (EPI == 0 || EPI == 2 || EPI == 3)
                    *(float2*)&C[(size_t)r * ldc + c] = make_float2(v0, v1);
                if (EPI == 1 || EPI == 2 || EPI == 4) {
                    u32 hp, lp2;
                    pack_split2(v0, v1, hp, lp2);
                    *(u32*)&Chb[(size_t)r * ldcb + c] = hp;
                    *(u32*)&Clb[(size_t)r * ldcb + c] = lp2;
                }
            }
        }
    }
}

// ---------------------------------------------------------------------------
// HMMA GEMM 64x64 tile (Wo, ff2), LDSM fragment loads. 128 threads, 4 warps.
// ---------------------------------------------------------------------------
template <int EPI>
__global__ void __launch_bounds__(128) mmagemm64_k(
    const __nv_bfloat16* __restrict__ Ah, const __nv_bfloat16* __restrict__ Al, int lda,
    const __nv_bfloat16* __restrict__ BTh, const __nv_bfloat16* __restrict__ BTl,
    int K,
    float* __restrict__ C, int ldc,
    __nv_bfloat16* __restrict__ Chb, __nv_bfloat16* __restrict__ Clb, int ldcb,
    const float* __restrict__ bias,
    const float* __restrict__ resid, int ldr,
    const float* __restrict__ alphap)
{
    __shared__ __align__(16) __nv_bfloat16 sAh[64 * GPAD];
    __shared__ __align__(16) __nv_bfloat16 sAl[64 * GPAD];
    __shared__ __align__(16) __nv_bfloat16 sBh[64 * GPAD];
    __shared__ __align__(16) __nv_bfloat16 sBl[64 * GPAD];

    const int tid  = threadIdx.x;
    const int warp = tid >> 5;
    const int lane = tid & 31;
    const int grp  = lane >> 2;
    const int tig  = lane & 3;
    const int wm   = warp & 1;
    const int wn   = warp >> 1;
    const int row0 = blockIdx.y * 64;
    const int col0 = blockIdx.x * 64;

    const int a_r0 = tid >> 2;
    const int a_k  = (tid & 3) * 8;
    const int a_dst0 = a_r0 * GPAD + a_k;

    const u32 sAh_u = s2u(sAh), sAl_u = s2u(sAl);
    const u32 sBh_u = s2u(sBh), sBl_u = s2u(sBl);
    const int aoff = (((lane & 15) * GPAD) + (lane >> 4) * 8) * 2;
    const int boff = ((((lane & 7) + ((lane >> 4) & 1) * 8) * GPAD) + ((lane >> 3) & 1) * 8) * 2;

    float acc[2][4][4];
#pragma unroll
    for (int mt = 0; mt < 2; mt++)
#pragma unroll
        for (int nt = 0; nt < 4; nt++)
#pragma unroll
            for (int i = 0; i < 4; i++) acc[mt][nt][i] = 0.f;

    uint4 pAh[2], pAl[2], pBh[2], pBl[2];
#pragma unroll
    for (int i = 0; i < 2; i++) {
        const size_t ga = (size_t)(row0 + a_r0 + i * 32) * lda + a_k;
        pAh[i] = *(const uint4*)(Ah + ga);
        pAl[i] = *(const uint4*)(Al + ga);
        const size_t gb = (size_t)(col0 + a_r0 + i * 32) * K + a_k;
        pBh[i] = *(const uint4*)(BTh + gb);
        pBl[i] = *(const uint4*)(BTl + gb);
    }

    const int nchunks = K >> 5;
    for (int kc = 0; kc < nchunks; kc++) {
#pragma unroll
        for (int i = 0; i < 2; i++) {
            *(uint4*)&sAh[a_dst0 + i * 32 * GPAD] = pAh[i];
            *(uint4*)&sAl[a_dst0 + i * 32 * GPAD] = pAl[i];
            *(uint4*)&sBh[a_dst0 + i * 32 * GPAD] = pBh[i];
            *(uint4*)&sBl[a_dst0 + i * 32 * GPAD] = pBl[i];
        }
        __syncthreads();

        if (kc + 1 < nchunks) {
            const int k0 = (kc + 1) * 32;
#pragma unroll
            for (int i = 0; i < 2; i++) {
                const size_t ga = (size_t)(row0 + a_r0 + i * 32) * lda + k0 + a_k;
                pAh[i] = *(const uint4*)(Ah + ga);
                pAl[i] = *(const uint4*)(Al + ga);
                const size_t gb = (size_t)(col0 + a_r0 + i * 32) * K + k0 + a_k;
                pBh[i] = *(const uint4*)(BTh + gb);
                pBl[i] = *(const uint4*)(BTl + gb);
            }
        }

#pragma unroll
        for (int ks = 0; ks < 32; ks += 16) {
            u32 ah[2][4], al[2][4];
#pragma unroll
            for (int mt = 0; mt < 2; mt++) {
                const int base = ((wm * 32 + mt * 16) * GPAD + ks) * 2;
                ldsm4(ah[mt], sAh_u + base + aoff);
                ldsm4(al[mt], sAl_u + base + aoff);
            }
            u32 bh[2][4], bl[2][4];
#pragma unroll
            for (int p = 0; p < 2; p++) {
                const int base = ((wn * 32 + p * 16) * GPAD + ks) * 2;
                ldsm4(bh[p], sBh_u + base + boff);
                ldsm4(bl[p], sBl_u + base + boff);
            }
#pragma unroll
            for (int mt = 0; mt < 2; mt++)
#pragma unroll
                for (int nt = 0; nt < 4; nt++) {
                    const u32* bhp = &bh[nt >> 1][(nt & 1) * 2];
                    const u32* blp = &bl[nt >> 1][(nt & 1) * 2];
                    mma16816(acc[mt][nt], ah[mt], bhp);
                    mma16816(acc[mt][nt], ah[mt], blp);
                    mma16816(acc[mt][nt], al[mt], bhp);
                }
        }
        __syncthreads();
    }

    float alpha = 0.f;
    if (EPI == 2 || EPI == 3) alpha = __ldg(alphap);

#pragma unroll
    for (int mt = 0; mt < 2; mt++) {
#pragma unroll
        for (int rh = 0; rh < 2; rh++) {
            const int r = row0 + wm * 32 + mt * 16 + grp + rh * 8;
#pragma unroll
            for (int nt = 0; nt < 4; nt++) {
                const int c = col0 + wn * 32 + nt * 8 + tig * 2;
                float v0 = acc[mt][nt][rh * 2 + 0];
                float v1 = acc[mt][nt][rh * 2 + 1];
                if (EPI == 1 || EPI == 3) {
                    float2 bb = *(const float2*)&bias[c];
                    v0 += bb.x; v1 += bb.y;
                }
                if (EPI == 1) {
                    v0 = fmaxf(v0, 0.f); v1 = fmaxf(v1, 0.f);
                }
                if (EPI == 2 || EPI == 3) {
                    float2 rv = *(const float2*)&resid[(size_t)r * ldr + c];
                    v0 = fmaf(alpha, v0, rv.x);
                    v1 = fmaf(alpha, v1, rv.y);
                }
                if (EPI == 0 || EPI == 2 || EPI == 3)
                    *(float2*)&C[(size_t)r * ldc + c] = make_float2(v0, v1);
                if (EPI == 1 || EPI == 2 || EPI == 4) {
                    u32 hp, lp2;
                    pack_split2(v0, v1, hp, lp2);
                    *(u32*)&Chb[(size_t)r * ldcb + c] = hp;
                    *(u32*)&Clb[(size_t)r * ldcb + c] = lp2;
                }
            }
        }
    }
}

// ---------------------------------------------------------------------------
// Prep: split x (elementwise)
// ---------------------------------------------------------------------------
__global__ void __launch_bounds__(256) split_x_k(
    const float* __restrict__ x, __nv_bfloat16* __restrict__ xh,
    __nv_bfloat16* __restrict__ xl, int n4)
{
    int i = blockIdx.x * 256 + threadIdx.x;
    if (i >= n4) return;
    float4 vv = ((const float4*)x)[i];
    float a[4] = { vv.x, vv.y, vv.z, vv.w };
    u16 hb[4], lb[4];
#pragma unroll
    for (int j = 0; j < 4; j++) bfsplit(a[j], hb[j], lb[j]);
    ((uint2*)xh)[i] = make_uint2((u32)hb[0] | ((u32)hb[1] << 16), (u32)hb[2] | ((u32)hb[3] << 16));
    ((uint2*)xl)[i] = make_uint2((u32)lb[0] | ((u32)lb[1] << 16), (u32)lb[2] | ((u32)lb[3] << 16));
}

// ---------------------------------------------------------------------------
// Prep: ALL weight transposes+splits, 192 blocks (round-8 verified).
// ---------------------------------------------------------------------------
__global__ void __launch_bounds__(256) wsplit_all_k(
    const float* __restrict__ Wq, const float* __restrict__ Wk,
    const float* __restrict__ Wv, const float* __restrict__ Wo,
    const float* __restrict__ W1, const float* __restrict__ W2,
    __nv_bfloat16* __restrict__ WqkvTh, __nv_bfloat16* __restrict__ WqkvTl,
    __nv_bfloat16* __restrict__ WoTh,   __nv_bfloat16* __restrict__ WoTl,
    __nv_bfloat16* __restrict__ W1Th,   __nv_bfloat16* __restrict__ W1Tl,
    __nv_bfloat16* __restrict__ W2Th,   __nv_bfloat16* __restrict__ W2Tl)
{
    __shared__ float sT[32][33];
    const int bid = blockIdx.x;
    const float* src;
    __nv_bfloat16 *dh, *dl;
    int N, k0, n0, ldo;
    if (bid < 48) {
        int widx = bid >> 4;
        int t = bid & 15;
        src = (widx == 0) ? Wq : (widx == 1) ? Wk : Wv;
        N = 128; k0 = (t >> 2) * 32; n0 = (t & 3) * 32; ldo = 128;
        dh = WqkvTh + widx * 128 * 128;
        dl = WqkvTl + widx * 128 * 128;
    } else if (bid < 64) {
        int t = bid - 48;
        src = Wo; N = 128; k0 = (t >> 2) * 32; n0 = (t & 3) * 32; ldo = 128;
        dh = WoTh; dl = WoTl;
    } else if (bid < 128) {
        int t = bid - 64;
        src = W1; N = 512; k0 = (t & 3) * 32; n0 = (t >> 2) * 32; ldo = 128;
        dh = W1Th; dl = W1Tl;
    } else {
        int t = bid - 128;
        src = W2; N = 128; k0 = (t >> 2) * 32; n0 = (t & 3) * 32; ldo = 512;
        dh = W2Th; dl = W2Tl;
    }

    const int r = threadIdx.x >> 5, c = threadIdx.x & 31;
#pragma unroll
    for (int i = 0; i < 4; i++)
        sT[r + 8 * i][c] = src[(size_t)(k0 + r + 8 * i) * N + n0 + c];
    __syncthreads();

#pragma unroll
    for (int i = 0; i < 2; i++) {
        int idx = threadIdx.x + i * 256;
        int orow = idx >> 4;
        int oc = (idx & 15) * 2;
        u32 hp, lp2;
        pack_split2(sT[oc][orow], sT[oc + 1][orow], hp, lp2);
        size_t o = (size_t)(n0 + orow) * ldo + k0 + oc;
        *(u32*)&dh[o] = hp;
        *(u32*)&dl[o] = lp2;
    }
}

// ---------------------------------------------------------------------------
// Flash attention on HMMA, NSPLIT=4 (round-14 geometry), V staged row-major
// and loaded via ldmatrix.x4.trans (round-15 V path, kept).
// __launch_bounds__(256, 4) keeps 4 blocks/SM resident.
// ---------------------------------------------------------------------------
#define KSTR 24
#define ESTR 72

__global__ void __launch_bounds__(256, 4) attn_mma_k(
    const __nv_bfloat16* __restrict__ qkvh, const __nv_bfloat16* __restrict__ qkvl,
    const float* __restrict__ e,
    float* __restrict__ attp, float* __restrict__ lp)
{
    __shared__ __align__(16) __nv_bfloat16 sKh[64 * KSTR], sKl[64 * KSTR];
    __shared__ __align__(16) __nv_bfloat16 sVh[64 * KSTR], sVl[64 * KSTR];
    __shared__ __align__(16) float es[128 * ESTR];     // 36 KB

    const int qt = blockIdx.x;
    const int h  = blockIdx.y;
    const int bz = blockIdx.z;
    const int b = bz >> 2, split = bz & 3;
    const int tid = threadIdx.x;
    const int w = tid >> 5, lane = tid & 31;
    const int grp = lane >> 2, tig = lane & 3;

    const int qrow = qt * 128 + w * 16 + grp;
    const size_t grow = (size_t)b * SEQ + qrow;

    u32 qfh[4], qfl[4];
    {
        const size_t b0 = grow * 384 + h * DH;
        const size_t b8 = (grow + 8) * 384 + h * DH;
        qfh[0] = *(const u32*)&qkvh[b0 + tig * 2];
        qfh[1] = *(const u32*)&qkvh[b8 + tig * 2];
        qfh[2] = *(const u32*)&qkvh[b0 + tig * 2 + 8];
        qfh[3] = *(const u32*)&qkvh[b8 + tig * 2 + 8];
        qfl[0] = *(const u32*)&qkvl[b0 + tig * 2];
        qfl[1] = *(const u32*)&qkvl[b8 + tig * 2];
        qfl[2] = *(const u32*)&qkvl[b0 + tig * 2 + 8];
        qfl[3] = *(const u32*)&qkvl[b8 + tig * 2 + 8];
    }

    float o0[4] = {0.f, 0.f, 0.f, 0.f};
    float o1[4] = {0.f, 0.f, 0.f, 0.f};
    float la = 0.f, lb = 0.f;

    // K/V staging ids (both uint4, V row-major like K)
    const int skey = tid & 63;
    const int ssel = (tid >> 6) & 1;
    const int shl  = tid >> 7;
    const __nv_bfloat16* ssrc = shl ? qkvl : qkvh;
    __nv_bfloat16* kdst = shl ? sKl : sKh;
    __nv_bfloat16* vdst = shl ? sVl : sVh;
    const int kvdsto = skey * KSTR + ssel * 8;

    // e staging ids (coalesced)
    const int e_row = tid >> 4;
    const int e_c16 = (tid & 15) * 4;
    const float* ebase = e + ((size_t)b * SEQ + qt * 128) * SEQ;

    const int er0 = (w * 16 + grp) * ESTR + tig * 2;
    const int er8 = er0 + 8 * ESTR;

    // LDSM per-lane offsets (bytes)
    const u32 sKh_u = s2u(sKh), sKl_u = s2u(sKl);
    const u32 sVh_u = s2u(sVh), sVl_u = s2u(sVl);
    const int kfoff = ((((lane & 7) + ((lane >> 4) & 1) * 8) * KSTR) + ((lane >> 3) & 1) * 8) * 2;
    const int vfoff = (((lane & 15) * KSTR) + (lane >> 4) * 8) * 2;

    const int kstart = split * (SEQ / NSPLIT);   // 256 keys per split

    for (int jc = 0; jc < (SEQ / NSPLIT) / 64; jc++) {   // 4 chunks
        const int k0 = kstart + jc * 64;
        __syncthreads();
        {
            const size_t g = ((size_t)b * SEQ + k0 + skey) * 384 + 128 + h * DH + ssel * 8;
            *(uint4*)&kdst[kvdsto] = *(const uint4*)&ssrc[g];
            *(uint4*)&vdst[kvdsto] = *(const uint4*)&ssrc[g + 128];
        }
#pragma unroll
        for (int i = 0; i < 8; i++) {
            int row = e_row + i * 16;
            uint4 ev = *(const uint4*)&ebase[(size_t)row * SEQ + k0 + e_c16];
            *(uint4*)&es[row * ESTR + e_c16] = ev;
        }
        __syncthreads();

        u32 ph0[8], ph8[8], pl0[8], pl8[8];
#pragma unroll
        for (int p = 0; p < 4; p++) {       // covers nt = 2p, 2p+1
            u32 kh[4], kl[4];
            ldsm4(kh, sKh_u + p * 16 * KSTR * 2 + kfoff);
            ldsm4(kl, sKl_u + p * 16 * KSTR * 2 + kfoff);
#pragma unroll
            for (int q = 0; q < 2; q++) {
                const int nt = 2 * p + q;
                float c[4] = {0.f, 0.f, 0.f, 0.f};
                mma16816(c, qfh, &kh[q * 2]);
                mma16816(c, qfh, &kl[q * 2]);
                mma16816(c, qfl, &kh[q * 2]);

                float2 e0 = *(const float2*)&es[er0 + nt * 8];
                float2 e8 = *(const float2*)&es[er8 + nt * 8];
                float w00 = expw(c[0], e0.x);
                float w01 = expw(c[1], e0.y);
                float w10 = expw(c[2], e8.x);
                float w11 = expw(c[3], e8.y);
                la += w00 + w01;
                lb += w10 + w11;
                pack_split2(w00, w01, ph0[nt], pl0[nt]);
                pack_split2(w10, w11, ph8[nt], pl8[nt]);
            }
        }

#pragma unroll
        for (int kc = 0; kc < 4; kc++) {
            u32 ah[4] = { ph0[2 * kc], ph8[2 * kc], ph0[2 * kc + 1], ph8[2 * kc + 1] };
            u32 al[4] = { pl0[2 * kc], pl8[2 * kc], pl0[2 * kc + 1], pl8[2 * kc + 1] };
            u32 vh[4], vl[4];   // trans: {n0k0-7, n0k8-15, n1k0-7, n1k8-15}
            ldsm4t(vh, sVh_u + kc * 16 * KSTR * 2 + vfoff);
            ldsm4t(vl, sVl_u + kc * 16 * KSTR * 2 + vfoff);
            mma16816(o0, ah, &vh[0]);
            mma16816(o1, ah, &vh[2]);
            mma16816(o0, al, &vh[0]);
            mma16816(o1, al, &vh[2]);
            mma16816(o0, ah, &vl[0]);
            mma16816(o1, ah, &vl[2]);
        }
    }

    la += __shfl_xor_sync(0xffffffffu, la, 1);
    la += __shfl_xor_sync(0xffffffffu, la, 2);
    lb += __shfl_xor_sync(0xffffffffu, lb, 1);
    lb += __shfl_xor_sync(0xffffffffu, lb, 2);

    float* opa = attp + ((size_t)split * MROWS + grow) * DIM + h * DH;
    float* opb = attp + ((size_t)split * MROWS + grow + 8) * DIM + h * DH;
    *(float2*)&opa[tig * 2]     = make_float2(o0[0], o0[1]);
    *(float2*)&opa[8 + tig * 2] = make_float2(o1[0], o1[1]);
    *(float2*)&opb[tig * 2]     = make_float2(o0[2], o0[3]);
    *(float2*)&opb[8 + tig * 2] = make_float2(o1[2], o1[3]);
    if (tig == 0) {
        lp[((size_t)split * MROWS + grow) * HEADS + h]     = la;
        lp[((size_t)split * MROWS + grow + 8) * HEADS + h] = lb;
    }
}

// ---------------------------------------------------------------------------
// Combine split partials -> normalized att as bf16 hi/lo (1024 blocks).
// ---------------------------------------------------------------------------
__global__ void __launch_bounds__(256) combine_k(
    const float* __restrict__ attp, const float* __restrict__ lp,
    __nv_bfloat16* __restrict__ ath, __nv_bfloat16* __restrict__ atl)
{
    int idx = blockIdx.x * 256 + threadIdx.x;
    int row = idx >> 5;
    int c4  = idx & 31;
    int h   = c4 >> 2;
    float4 s = make_float4(0.f, 0.f, 0.f, 0.f);
    float l = 0.f;
#pragma unroll
    for (int sp = 0; sp < NSPLIT; sp++) {
        float4 vv = *(const float4*)&attp[((size_t)sp * MROWS + row) * DIM + c4 * 4];
        s.x += vv.x; s.y += vv.y; s.z += vv.z; s.w += vv.w;
        l += lp[((size_t)sp * MROWS + row) * HEADS + h];
    }
    float inv = 1.0f / l;
    u32 hp, lp2;
    pack_split2(s.x * inv, s.y * inv, hp, lp2);
    *(u32*)&ath[(size_t)row * DIM + c4 * 4]     = hp;
    *(u32*)&atl[(size_t)row * DIM + c4 * 4]     = lp2;
    pack_split2(s.z * inv, s.w * inv, hp, lp2);
    *(u32*)&ath[(size_t)row * DIM + c4 * 4 + 2] = hp;
    *(u32*)&atl[(size_t)row * DIM + c4 * 4 + 2] = lp2;
}

// ---------------------------------------------------------------------------
// Launch
// ---------------------------------------------------------------------------
extern "C" void kernel_launch(void* const* d_in, const int* in_sizes, int n_in,
                              void* d_out, int out_size)
{
    const float* x  = (const float*)d_in[0];
    const float* e  = (const float*)d_in[1];
    const float* Wq = (const float*)d_in[2];
    const float* Wk = (const float*)d_in[3];
    const float* Wv = (const float*)d_in[4];
    const float* Wo = (const float*)d_in[5];
    const float* W1 = (const float*)d_in[6];
    const float* b1 = (const float*)d_in[7];
    const float* W2 = (const float*)d_in[8];
    const float* b2 = (const float*)d_in[9];
    const float* alpha1 = (const float*)d_in[10];
    const float* alpha2 = (const float*)d_in[11];
    float* out = (float*)d_out;

    float *x1, *attp, *lpv;
    __nv_bfloat16 *qkvh, *qkvl, *xh, *xl, *ath, *atl, *x1h, *x1l, *ffh, *ffl;
    __nv_bfloat16 *WqkvTh, *WqkvTl, *WoTh, *WoTl, *W1Th, *W1Tl, *W2Th, *W2Tl;
    cudaGetSymbolAddress((void**)&x1,   g_x1);
    cudaGetSymbolAddress((void**)&attp, g_attp);
    cudaGetSymbolAddress((void**)&lpv,  g_lp);
    cudaGetSymbolAddress((void**)&qkvh, g_qkvh);
    cudaGetSymbolAddress((void**)&qkvl, g_qkvl);
    cudaGetSymbolAddress((void**)&xh,   g_xh);
    cudaGetSymbolAddress((void**)&xl,   g_xl);
    cudaGetSymbolAddress((void**)&ath,  g_ath);
    cudaGetSymbolAddress((void**)&atl,  g_atl);
    cudaGetSymbolAddress((void**)&x1h,  g_x1h);
    cudaGetSymbolAddress((void**)&x1l,  g_x1l);
    cudaGetSymbolAddress((void**)&ffh,  g_ffh);
    cudaGetSymbolAddress((void**)&ffl,  g_ffl);
    cudaGetSymbolAddress((void**)&WqkvTh, g_WqkvTh);
    cudaGetSymbolAddress((void**)&WqkvTl, g_WqkvTl);
    cudaGetSymbolAddress((void**)&WoTh, g_WoTh);
    cudaGetSymbolAddress((void**)&WoTl, g_WoTl);
    cudaGetSymbolAddress((void**)&W1Th, g_W1Th);
    cudaGetSymbolAddress((void**)&W1Tl, g_W1Tl);
    cudaGetSymbolAddress((void**)&W2Th, g_W2Th);
    cudaGetSymbolAddress((void**)&W2Tl, g_W2Tl);

    // preps (2 launches)
    split_x_k<<<(MROWS * DIM / 4 + 255) / 256, 256>>>(x, xh, xl, MROWS * DIM / 4);
    wsplit_all_k<<<192, 256>>>(Wq, Wk, Wv, Wo, W1, W2,
                               WqkvTh, WqkvTl, WoTh, WoTl,
                               W1Th, W1Tl, W2Th, W2Tl);

    // qkv = x @ [Wq|Wk|Wv] -> bf16 hi/lo (ldcb=384); grid 384 blocks
    mmagemm_k<4><<<dim3(384 / 64, MROWS / 128), 256>>>(
        xh, xl, DIM, WqkvTh, WqkvTl, DIM,
        nullptr, 0, qkvh, qkvl, 384, nullptr, nullptr, 0, nullptr);

    // flash attention with 4-way key splits (2048 blocks)
    attn_mma_k<<<dim3(SEQ / 128, HEADS, BATCH * NSPLIT), 256>>>(qkvh, qkvl, e, attp, lpv);
    combine_k<<<(MROWS * DIM / 4) / 256, 256>>>(attp, lpv, ath, atl);

    // x1 = x + a1*(att @ Wo): 64x64 tiles, grid 256 blocks
    mmagemm64_k<2><<<dim3(DIM / 64, MROWS / 64), 128>>>(
        ath, atl, DIM, WoTh, WoTl, DIM,
        x1, DIM, x1h, x1l, DIM, nullptr, x, DIM, alpha1);

    // ff = relu(x1 @ W1 + b1): grid 512 blocks
    mmagemm_k<1><<<dim3(FFDIM / 64, MROWS / 128), 256>>>(
        x1h, x1l, DIM, W1Th, W1Tl, DIM,
        nullptr, 0, ffh, ffl, FFDIM, b1, nullptr, 0, nullptr);

    // out = x1 + a2*(ff @ W2 + b2): 64x64 tiles, grid 256 blocks
    mmagemm64_k<3><<<dim3(DIM / 64, MROWS / 64), 128>>>(
        ffh, ffl, FFDIM, W2Th, W2Tl, FFDIM,
        out, DIM, nullptr, nullptr, 0, b2, x1, DIM, alpha2);
}

// round 17
// speedup vs baseline: 1.1090x; 1.0397x over previous
#include <cuda_runtime.h>
#include <cuda_bf16.h>
#include <cstdint>

// Problem constants
#define BATCH 8
#define SEQ   1024
#define DIM   128
#define HEADS 8
#define DH    16
#define FFDIM 512
#define MROWS (BATCH*SEQ)   // 8192
#define NSPLIT 4

typedef unsigned long long u64;
typedef unsigned int u32;
typedef unsigned short u16;

// ------------------------- scratch (static only) ---------------------------
__device__ __align__(16) float g_x1  [MROWS * DIM];
__device__ __align__(16) float g_attp[NSPLIT * MROWS * DIM];
__device__ __align__(16) float g_lp  [NSPLIT * MROWS * HEADS];
// bf16 hi/lo split operands
__device__ __align__(16) __nv_bfloat16 g_qkvh[MROWS * 384], g_qkvl[MROWS * 384];
__device__ __align__(16) __nv_bfloat16 g_xh [MROWS * DIM],  g_xl [MROWS * DIM];
__device__ __align__(16) __nv_bfloat16 g_ath[MROWS * DIM],  g_atl[MROWS * DIM];
__device__ __align__(16) __nv_bfloat16 g_x1h[MROWS * DIM],  g_x1l[MROWS * DIM];
__device__ __align__(16) __nv_bfloat16 g_ffh[MROWS * FFDIM],g_ffl[MROWS * FFDIM];
// transposed + split weights: [N x K] K-major
__device__ __align__(16) __nv_bfloat16 g_WqkvTh[384 * DIM], g_WqkvTl[384 * DIM];
__device__ __align__(16) __nv_bfloat16 g_WoTh [DIM * DIM],  g_WoTl [DIM * DIM];
__device__ __align__(16) __nv_bfloat16 g_W1Th [FFDIM * DIM],g_W1Tl [FFDIM * DIM];
__device__ __align__(16) __nv_bfloat16 g_W2Th [DIM * FFDIM],g_W2Tl [DIM * FFDIM];

// ------------------------------ helpers ------------------------------------
__device__ __forceinline__ float ex2f(float x) {
    float y; asm("ex2.approx.f32 %0, %1;" : "=f"(y) : "f"(x)); return y;
}
__device__ __forceinline__ float rcpf(float x) {
    float y; asm("rcp.approx.f32 %0, %1;" : "=f"(y) : "f"(x)); return y;
}
__device__ __forceinline__ void bfsplit(float v, u16& hb, u16& lb) {
    __nv_bfloat16 h = __float2bfloat16(v);
    float rh = __bfloat162float(h);
    __nv_bfloat16 l = __float2bfloat16(v - rh);
    hb = *reinterpret_cast<u16*>(&h);
    lb = *reinterpret_cast<u16*>(&l);
}
// pack (w0 -> low 16, w1 -> high 16) bf16 hi + residual lo
__device__ __forceinline__ void pack_split2(float w0, float w1, u32& hp, u32& lp2) {
    __nv_bfloat162 hh = __floats2bfloat162_rn(w0, w1);
    float2 back = __bfloat1622float2(hh);
    __nv_bfloat162 ll = __floats2bfloat162_rn(w0 - back.x, w1 - back.y);
    hp  = *reinterpret_cast<u32*>(&hh);
    lp2 = *reinterpret_cast<u32*>(&ll);
}
// plain bf16x2 pack (hi only)
__device__ __forceinline__ u32 pack_bf2(float w0, float w1) {
    __nv_bfloat162 hh = __floats2bfloat162_rn(w0, w1);
    return *reinterpret_cast<u32*>(&hh);
}
// w = exp(10*tanh(dot/4 + ev) - 10), fixed-max softmax weight
__device__ __forceinline__ float expw(float dot, float ev) {
    float t = ex2f(fmaf(dot, 0.72134752f, ev * 2.8853901f));
    float u = rcpf(t + 1.0f);
    return ex2f(-28.8539008f * u);
}
// mma.sync m16n8k16 bf16 -> f32 accumulate in place
__device__ __forceinline__ void mma16816(float* c, const u32* a, const u32* b) {
    asm volatile(
        "mma.sync.aligned.m16n8k16.row.col.f32.bf16.bf16.f32 "
        "{%0,%1,%2,%3}, {%4,%5,%6,%7}, {%8,%9}, {%0,%1,%2,%3};"
        : "+f"(c[0]), "+f"(c[1]), "+f"(c[2]), "+f"(c[3])
        : "r"(a[0]), "r"(a[1]), "r"(a[2]), "r"(a[3]), "r"(b[0]), "r"(b[1]));
}
// shared-space address
__device__ __forceinline__ u32 s2u(const void* p) {
    u32 a; asm("{ .reg .u64 t; cvta.to.shared.u64 t, %1; cvt.u32.u64 %0, t; }"
               : "=r"(a) : "l"(p)); return a;
}
// ldmatrix x4
__device__ __forceinline__ void ldsm4(u32* r, u32 a) {
    asm volatile("ldmatrix.sync.aligned.m8n8.x4.shared.b16 {%0,%1,%2,%3}, [%4];"
                 : "=r"(r[0]), "=r"(r[1]), "=r"(r[2]), "=r"(r[3]) : "r"(a));
}
// ldmatrix x4 transposed (for B-fragments from row-major [k][n] tiles)
__device__ __forceinline__ void ldsm4t(u32* r, u32 a) {
    asm volatile("ldmatrix.sync.aligned.m8n8.x4.trans.shared.b16 {%0,%1,%2,%3}, [%4];"
                 : "=r"(r[0]), "=r"(r[1]), "=r"(r[2]), "=r"(r[3]) : "r"(a));
}

#define GPAD 40

// ---------------------------------------------------------------------------
// HMMA GEMM 128x64 tile, LDSM fragment loads. 256 threads, 8 warps (4x2).
// EPI: 0 fp32 | 1 relu(acc+bias)->bf16 h/l | 2 resid+alpha*acc -> fp32+h/l
//      3 resid+alpha*(acc+bias) -> fp32 | 4 plain bf16 h/l
// ---------------------------------------------------------------------------
template <int EPI>
__global__ void __launch_bounds__(256) mmagemm_k(
    const __nv_bfloat16* __restrict__ Ah, const __nv_bfloat16* __restrict__ Al, int lda,
    const __nv_bfloat16* __restrict__ BTh, const __nv_bfloat16* __restrict__ BTl,
    int K,
    float* __restrict__ C, int ldc,
    __nv_bfloat16* __restrict__ Chb, __nv_bfloat16* __restrict__ Clb, int ldcb,
    const float* __restrict__ bias,
    const float* __restrict__ resid, int ldr,
    const float* __restrict__ alphap)
{
    __shared__ __align__(16) __nv_bfloat16 sAh[128 * GPAD];
    __shared__ __align__(16) __nv_bfloat16 sAl[128 * GPAD];
    __shared__ __align__(16) __nv_bfloat16 sBh[64 * GPAD];
    __shared__ __align__(16) __nv_bfloat16 sBl[64 * GPAD];

    const int tid  = threadIdx.x;
    const int warp = tid >> 5;
    const int lane = tid & 31;
    const int grp  = lane >> 2;
    const int tig  = lane & 3;
    const int wm   = warp & 3;
    const int wn   = warp >> 2;
    const int row0 = blockIdx.y * 128;
    const int col0 = blockIdx.x * 64;

    const int a_r0 = tid >> 2;
    const int a_k  = (tid & 3) * 8;
    const int b_n  = tid >> 2;
    const int b_k  = (tid & 3) * 8;
    const int a_dst0 = a_r0 * GPAD + a_k;
    const int b_dst  = b_n * GPAD + b_k;

    const u32 sAh_u = s2u(sAh), sAl_u = s2u(sAl);
    const u32 sBh_u = s2u(sBh), sBl_u = s2u(sBl);
    const int aoff = (((lane & 15) * GPAD) + (lane >> 4) * 8) * 2;
    const int boff = ((((lane & 7) + ((lane >> 4) & 1) * 8) * GPAD) + ((lane >> 3) & 1) * 8) * 2;

    float acc[2][4][4];
#pragma unroll
    for (int mt = 0; mt < 2; mt++)
#pragma unroll
        for (int nt = 0; nt < 4; nt++)
#pragma unroll
            for (int i = 0; i < 4; i++) acc[mt][nt][i] = 0.f;

    uint4 pAh[2], pAl[2], pBh, pBl;
#pragma unroll
    for (int i = 0; i < 2; i++) {
        const size_t go = (size_t)(row0 + a_r0 + i * 64) * lda + a_k;
        pAh[i] = *(const uint4*)(Ah + go);
        pAl[i] = *(const uint4*)(Al + go);
    }
    {
        const size_t go = (size_t)(col0 + b_n) * K + b_k;
        pBh = *(const uint4*)(BTh + go);
        pBl = *(const uint4*)(BTl + go);
    }

    const int nchunks = K >> 5;
    for (int kc = 0; kc < nchunks; kc++) {
#pragma unroll
        for (int i = 0; i < 2; i++) {
            *(uint4*)&sAh[a_dst0 + i * 64 * GPAD] = pAh[i];
            *(uint4*)&sAl[a_dst0 + i * 64 * GPAD] = pAl[i];
        }
        *(uint4*)&sBh[b_dst] = pBh;
        *(uint4*)&sBl[b_dst] = pBl;
        __syncthreads();

        if (kc + 1 < nchunks) {
            const int k0 = (kc + 1) * 32;
#pragma unroll
            for (int i = 0; i < 2; i++) {
                const size_t go = (size_t)(row0 + a_r0 + i * 64) * lda + k0 + a_k;
                pAh[i] = *(const uint4*)(Ah + go);
                pAl[i] = *(const uint4*)(Al + go);
            }
            const size_t go = (size_t)(col0 + b_n) * K + k0 + b_k;
            pBh = *(const uint4*)(BTh + go);
            pBl = *(const uint4*)(BTl + go);
        }

#pragma unroll
        for (int ks = 0; ks < 32; ks += 16) {
            u32 ah[2][4], al[2][4];
#pragma unroll
            for (int mt = 0; mt < 2; mt++) {
                const int base = ((wm * 32 + mt * 16) * GPAD + ks) * 2;
                ldsm4(ah[mt], sAh_u + base + aoff);
                ldsm4(al[mt], sAl_u + base + aoff);
            }
            u32 bh[2][4], bl[2][4];
#pragma unroll
            for (int p = 0; p < 2; p++) {
                const int base = ((wn * 32 + p * 16) * GPAD + ks) * 2;
                ldsm4(bh[p], sBh_u + base + boff);
                ldsm4(bl[p], sBl_u + base + boff);
            }
#pragma unroll
            for (int mt = 0; mt < 2; mt++)
#pragma unroll
                for (int nt = 0; nt < 4; nt++) {
                    const u32* bhp = &bh[nt >> 1][(nt & 1) * 2];
                    const u32* blp = &bl[nt >> 1][(nt & 1) * 2];
                    mma16816(acc[mt][nt], ah[mt], bhp);
                    mma16816(acc[mt][nt], ah[mt], blp);
                    mma16816(acc[mt][nt], al[mt], bhp);
                }
        }
        __syncthreads();
    }

    float alpha = 0.f;
    if (EPI == 2 || EPI == 3) alpha = __ldg(alphap);

#pragma unroll
    for (int mt = 0; mt < 2; mt++) {
#pragma unroll
        for (int rh = 0; rh < 2; rh++) {
            const int r = row0 + wm * 32 + mt * 16 + grp + rh * 8;
#pragma unroll
            for (int nt = 0; nt < 4; nt++) {
                const int c = col0 + wn * 32 + nt * 8 + tig * 2;
                float v0 = acc[mt][nt][rh * 2 + 0];
                float v1 = acc[mt][nt][rh * 2 + 1];
                if (EPI == 1 || EPI == 3) {
                    float2 bb = *(const float2*)&bias[c];
                    v0 += bb.x; v1 += bb.y;
                }
                if (EPI == 1) {
                    v0 = fmaxf(v0, 0.f); v1 = fmaxf(v1, 0.f);
                }
                if (EPI == 2 || EPI == 3) {
                    float2 rv = *(const float2*)&resid[(size_t)r * ldr + c];
                    v0 = fmaf(alpha, v0, rv.x);
                    v1 = fmaf(alpha, v1, rv.y);
                }
                if (EPI == 0 || EPI == 2 || EPI == 3)
                    *(float2*)&C[(size_t)r * ldc + c] = make_float2(v0, v1);
                if (EPI == 1 || EPI == 2 || EPI == 4) {
                    u32 hp, lp2;
                    pack_split2(v0, v1, hp, lp2);
                    *(u32*)&Chb[(size_t)r * ldcb + c] = hp;
                    *(u32*)&Clb[(size_t)r * ldcb + c] = lp2;
                }
            }
        }
    }
}

// ---------------------------------------------------------------------------
// HMMA GEMM 64x64 tile (Wo, ff2), LDSM fragment loads. 128 threads, 4 warps.
// ---------------------------------------------------------------------------
template <int EPI>
__global__ void __launch_bounds__(128) mmagemm64_k(
    const __nv_bfloat16* __restrict__ Ah, const __nv_bfloat16* __restrict__ Al, int lda,
    const __nv_bfloat16* __restrict__ BTh, const __nv_bfloat16* __restrict__ BTl,
    int K,
    float* __restrict__ C, int ldc,
    __nv_bfloat16* __restrict__ Chb, __nv_bfloat16* __restrict__ Clb, int ldcb,
    const float* __restrict__ bias,
    const float* __restrict__ resid, int ldr,
    const float* __restrict__ alphap)
{
    __shared__ __align__(16) __nv_bfloat16 sAh[64 * GPAD];
    __shared__ __align__(16) __nv_bfloat16 sAl[64 * GPAD];
    __shared__ __align__(16) __nv_bfloat16 sBh[64 * GPAD];
    __shared__ __align__(16) __nv_bfloat16 sBl[64 * GPAD];

    const int tid  = threadIdx.x;
    const int warp = tid >> 5;
    const int lane = tid & 31;
    const int grp  = lane >> 2;
    const int tig  = lane & 3;
    const int wm   = warp & 1;
    const int wn   = warp >> 1;
    const int row0 = blockIdx.y * 64;
    const int col0 = blockIdx.x * 64;

    const int a_r0 = tid >> 2;
    const int a_k  = (tid & 3) * 8;
    const int a_dst0 = a_r0 * GPAD + a_k;

    const u32 sAh_u = s2u(sAh), sAl_u = s2u(sAl);
    const u32 sBh_u = s2u(sBh), sBl_u = s2u(sBl);
    const int aoff = (((lane & 15) * GPAD) + (lane >> 4) * 8) * 2;
    const int boff = ((((lane & 7) + ((lane >> 4) & 1) * 8) * GPAD) + ((lane >> 3) & 1) * 8) * 2;

    float acc[2][4][4];
#pragma unroll
    for (int mt = 0; mt < 2; mt++)
#pragma unroll
        for (int nt = 0; nt < 4; nt++)
#pragma unroll
            for (int i = 0; i < 4; i++) acc[mt][nt][i] = 0.f;

    uint4 pAh[2], pAl[2], pBh[2], pBl[2];
#pragma unroll
    for (int i = 0; i < 2; i++) {
        const size_t ga = (size_t)(row0 + a_r0 + i * 32) * lda + a_k;
        pAh[i] = *(const uint4*)(Ah + ga);
        pAl[i] = *(const uint4*)(Al + ga);
        const size_t gb = (size_t)(col0 + a_r0 + i * 32) * K + a_k;
        pBh[i] = *(const uint4*)(BTh + gb);
        pBl[i] = *(const uint4*)(BTl + gb);
    }

    const int nchunks = K >> 5;
    for (int kc = 0; kc < nchunks; kc++) {
#pragma unroll
        for (int i = 0; i < 2; i++) {
            *(uint4*)&sAh[a_dst0 + i * 32 * GPAD] = pAh[i];
            *(uint4*)&sAl[a_dst0 + i * 32 * GPAD] = pAl[i];
            *(uint4*)&sBh[a_dst0 + i * 32 * GPAD] = pBh[i];
            *(uint4*)&sBl[a_dst0 + i * 32 * GPAD] = pBl[i];
        }
        __syncthreads();

        if (kc + 1 < nchunks) {
            const int k0 = (kc + 1) * 32;
#pragma unroll
            for (int i = 0; i < 2; i++) {
                const size_t ga = (size_t)(row0 + a_r0 + i * 32) * lda + k0 + a_k;
                pAh[i] = *(const uint4*)(Ah + ga);
                pAl[i] = *(const uint4*)(Al + ga);
                const size_t gb = (size_t)(col0 + a_r0 + i * 32) * K + k0 + a_k;
                pBh[i] = *(const uint4*)(BTh + gb);
                pBl[i] = *(const uint4*)(BTl + gb);
            }
        }

#pragma unroll
        for (int ks = 0; ks < 32; ks += 16) {
            u32 ah[2][4], al[2][4];
#pragma unroll
            for (int mt = 0; mt < 2; mt++) {
                const int base = ((wm * 32 + mt * 16) * GPAD + ks) * 2;
                ldsm4(ah[mt], sAh_u + base + aoff);
                ldsm4(al[mt], sAl_u + base + aoff);
            }
            u32 bh[2][4], bl[2][4];
#pragma unroll
            for (int p = 0; p < 2; p++) {
                const int base = ((wn * 32 + p * 16) * GPAD + ks) * 2;
                ldsm4(bh[p], sBh_u + base + boff);
                ldsm4(bl[p], sBl_u + base + boff);
            }
#pragma unroll
            for (int mt = 0; mt < 2; mt++)
#pragma unroll
                for (int nt = 0; nt < 4; nt++) {
                    const u32* bhp = &bh[nt >> 1][(nt & 1) * 2];
                    const u32* blp = &bl[nt >> 1][(nt & 1) * 2];
                    mma16816(acc[mt][nt], ah[mt], bhp);
                    mma16816(acc[mt][nt], ah[mt], blp);
                    mma16816(acc[mt][nt], al[mt], bhp);
                }
        }
        __syncthreads();
    }

    float alpha = 0.f;
    if (EPI == 2 || EPI == 3) alpha = __ldg(alphap);

#pragma unroll
    for (int mt = 0; mt < 2; mt++) {
#pragma unroll
        for (int rh = 0; rh < 2; rh++) {
            const int r = row0 + wm * 32 + mt * 16 + grp + rh * 8;
#pragma unroll
            for (int nt = 0; nt < 4; nt++) {
                const int c = col0 + wn * 32 + nt * 8 + tig * 2;
                float v0 = acc[mt][nt][rh * 2 + 0];
                float v1 = acc[mt][nt][rh * 2 + 1];
                if (EPI == 1 || EPI == 3) {
                    float2 bb = *(const float2*)&bias[c];
                    v0 += bb.x; v1 += bb.y;
                }
                if (EPI == 1) {
                    v0 = fmaxf(v0, 0.f); v1 = fmaxf(v1, 0.f);
                }
                if (EPI == 2 || EPI == 3) {
                    float2 rv = *(const float2*)&resid[(size_t)r * ldr + c];
                    v0 = fmaf(alpha, v0, rv.x);
                    v1 = fmaf(alpha, v1, rv.y);
                }
                if (EPI == 0 || EPI == 2 || EPI == 3)
                    *(float2*)&C[(size_t)r * ldc + c] = make_float2(v0, v1);
                if (EPI == 1 || EPI == 2 || EPI == 4) {
                    u32 hp, lp2;
                    pack_split2(v0, v1, hp, lp2);
                    *(u32*)&Chb[(size_t)r * ldcb + c] = hp;
                    *(u32*)&Clb[(size_t)r * ldcb + c] = lp2;
                }
            }
        }
    }
}

// ---------------------------------------------------------------------------
// Prep: split x (elementwise)
// ---------------------------------------------------------------------------
__global__ void __launch_bounds__(256) split_x_k(
    const float* __restrict__ x, __nv_bfloat16* __restrict__ xh,
    __nv_bfloat16* __restrict__ xl, int n4)
{
    int i = blockIdx.x * 256 + threadIdx.x;
    if (i >= n4) return;
    float4 vv = ((const float4*)x)[i];
    float a[4] = { vv.x, vv.y, vv.z, vv.w };
    u16 hb[4], lb[4];
#pragma unroll
    for (int j = 0; j < 4; j++) bfsplit(a[j], hb[j], lb[j]);
    ((uint2*)xh)[i] = make_uint2((u32)hb[0] | ((u32)hb[1] << 16), (u32)hb[2] | ((u32)hb[3] << 16));
    ((uint2*)xl)[i] = make_uint2((u32)lb[0] | ((u32)lb[1] << 16), (u32)lb[2] | ((u32)lb[3] << 16));
}

// ---------------------------------------------------------------------------
// Prep: ALL weight transposes+splits, 192 blocks (round-8 verified).
// ---------------------------------------------------------------------------
__global__ void __launch_bounds__(256) wsplit_all_k(
    const float* __restrict__ Wq, const float* __restrict__ Wk,
    const float* __restrict__ Wv, const float* __restrict__ Wo,
    const float* __restrict__ W1, const float* __restrict__ W2,
    __nv_bfloat16* __restrict__ WqkvTh, __nv_bfloat16* __restrict__ WqkvTl,
    __nv_bfloat16* __restrict__ WoTh,   __nv_bfloat16* __restrict__ WoTl,
    __nv_bfloat16* __restrict__ W1Th,   __nv_bfloat16* __restrict__ W1Tl,
    __nv_bfloat16* __restrict__ W2Th,   __nv_bfloat16* __restrict__ W2Tl)
{
    __shared__ float sT[32][33];
    const int bid = blockIdx.x;
    const float* src;
    __nv_bfloat16 *dh, *dl;
    int N, k0, n0, ldo;
    if (bid < 48) {
        int widx = bid >> 4;
        int t = bid & 15;
        src = (widx == 0) ? Wq : (widx == 1) ? Wk : Wv;
        N = 128; k0 = (t >> 2) * 32; n0 = (t & 3) * 32; ldo = 128;
        dh = WqkvTh + widx * 128 * 128;
        dl = WqkvTl + widx * 128 * 128;
    } else if (bid < 64) {
        int t = bid - 48;
        src = Wo; N = 128; k0 = (t >> 2) * 32; n0 = (t & 3) * 32; ldo = 128;
        dh = WoTh; dl = WoTl;
    } else if (bid < 128) {
        int t = bid - 64;
        src = W1; N = 512; k0 = (t & 3) * 32; n0 = (t >> 2) * 32; ldo = 128;
        dh = W1Th; dl = W1Tl;
    } else {
        int t = bid - 128;
        src = W2; N = 128; k0 = (t >> 2) * 32; n0 = (t & 3) * 32; ldo = 512;
        dh = W2Th; dl = W2Tl;
    }

    const int r = threadIdx.x >> 5, c = threadIdx.x & 31;
#pragma unroll
    for (int i = 0; i < 4; i++)
        sT[r + 8 * i][c] = src[(size_t)(k0 + r + 8 * i) * N + n0 + c];
    __syncthreads();

#pragma unroll
    for (int i = 0; i < 2; i++) {
        int idx = threadIdx.x + i * 256;
        int orow = idx >> 4;
        int oc = (idx & 15) * 2;
        u32 hp, lp2;
        pack_split2(sT[oc][orow], sT[oc + 1][orow], hp, lp2);
        size_t o = (size_t)(n0 + orow) * ldo + k0 + oc;
        *(u32*)&dh[o] = hp;
        *(u32*)&dl[o] = lp2;
    }
}

// ---------------------------------------------------------------------------
// Flash attention on HMMA, NSPLIT=4, ldsm4t V path. P kept hi-only (bf16):
// denominator uses exact fp32 w, so normalization is unbiased; numerator
// rounding is ~2^-10 RMS relative — well under the 1e-3 budget. Saves
// 16 pack_split2 -> 8 cvt per thread-chunk and 8 AV MMAs.
// ---------------------------------------------------------------------------
#define KSTR 24
#define ESTR 72

__global__ void __launch_bounds__(256, 4) attn_mma_k(
    const __nv_bfloat16* __restrict__ qkvh, const __nv_bfloat16* __restrict__ qkvl,
    const float* __restrict__ e,
    float* __restrict__ attp, float* __restrict__ lp)
{
    __shared__ __align__(16) __nv_bfloat16 sKh[64 * KSTR], sKl[64 * KSTR];
    __shared__ __align__(16) __nv_bfloat16 sVh[64 * KSTR], sVl[64 * KSTR];
    __shared__ __align__(16) float es[128 * ESTR];     // 36 KB

    const int qt = blockIdx.x;
    const int h  = blockIdx.y;
    const int bz = blockIdx.z;
    const int b = bz >> 2, split = bz & 3;
    const int tid = threadIdx.x;
    const int w = tid >> 5, lane = tid & 31;
    const int grp = lane >> 2, tig = lane & 3;

    const int qrow = qt * 128 + w * 16 + grp;
    const size_t grow = (size_t)b * SEQ + qrow;

    u32 qfh[4], qfl[4];
    {
        const size_t b0 = grow * 384 + h * DH;
        const size_t b8 = (grow + 8) * 384 + h * DH;
        qfh[0] = *(const u32*)&qkvh[b0 + tig * 2];
        qfh[1] = *(const u32*)&qkvh[b8 + tig * 2];
        qfh[2] = *(const u32*)&qkvh[b0 + tig * 2 + 8];
        qfh[3] = *(const u32*)&qkvh[b8 + tig * 2 + 8];
        qfl[0] = *(const u32*)&qkvl[b0 + tig * 2];
        qfl[1] = *(const u32*)&qkvl[b8 + tig * 2];
        qfl[2] = *(const u32*)&qkvl[b0 + tig * 2 + 8];
        qfl[3] = *(const u32*)&qkvl[b8 + tig * 2 + 8];
    }

    float o0[4] = {0.f, 0.f, 0.f, 0.f};
    float o1[4] = {0.f, 0.f, 0.f, 0.f};
    float la = 0.f, lb = 0.f;

    // K/V staging ids (both uint4, V row-major like K)
    const int skey = tid & 63;
    const int ssel = (tid >> 6) & 1;
    const int shl  = tid >> 7;
    const __nv_bfloat16* ssrc = shl ? qkvl : qkvh;
    __nv_bfloat16* kdst = shl ? sKl : sKh;
    __nv_bfloat16* vdst = shl ? sVl : sVh;
    const int kvdsto = skey * KSTR + ssel * 8;

    // e staging ids (coalesced)
    const int e_row = tid >> 4;
    const int e_c16 = (tid & 15) * 4;
    const float* ebase = e + ((size_t)b * SEQ + qt * 128) * SEQ;

    const int er0 = (w * 16 + grp) * ESTR + tig * 2;
    const int er8 = er0 + 8 * ESTR;

    // LDSM per-lane offsets (bytes)
    const u32 sKh_u = s2u(sKh), sKl_u = s2u(sKl);
    const u32 sVh_u = s2u(sVh), sVl_u = s2u(sVl);
    const int kfoff = ((((lane & 7) + ((lane >> 4) & 1) * 8) * KSTR) + ((lane >> 3) & 1) * 8) * 2;
    const int vfoff = (((lane & 15) * KSTR) + (lane >> 4) * 8) * 2;

    const int kstart = split * (SEQ / NSPLIT);   // 256 keys per split

    for (int jc = 0; jc < (SEQ / NSPLIT) / 64; jc++) {   // 4 chunks
        const int k0 = kstart + jc * 64;
        __syncthreads();
        {
            const size_t g = ((size_t)b * SEQ + k0 + skey) * 384 + 128 + h * DH + ssel * 8;
            *(uint4*)&kdst[kvdsto] = *(const uint4*)&ssrc[g];
            *(uint4*)&vdst[kvdsto] = *(const uint4*)&ssrc[g + 128];
        }
#pragma unroll
        for (int i = 0; i < 8; i++) {
            int row = e_row + i * 16;
            uint4 ev = *(const uint4*)&ebase[(size_t)row * SEQ + k0 + e_c16];
            *(uint4*)&es[row * ESTR + e_c16] = ev;
        }
        __syncthreads();

        u32 ph0[8], ph8[8];
#pragma unroll
        for (int p = 0; p < 4; p++) {       // covers nt = 2p, 2p+1
            u32 kh[4], kl[4];
            ldsm4(kh, sKh_u + p * 16 * KSTR * 2 + kfoff);
            ldsm4(kl, sKl_u + p * 16 * KSTR * 2 + kfoff);
#pragma unroll
            for (int q = 0; q < 2; q++) {
                const int nt = 2 * p + q;
                float c[4] = {0.f, 0.f, 0.f, 0.f};
                mma16816(c, qfh, &kh[q * 2]);
                mma16816(c, qfh, &kl[q * 2]);
                mma16816(c, qfl, &kh[q * 2]);

                float2 e0 = *(const float2*)&es[er0 + nt * 8];
                float2 e8 = *(const float2*)&es[er8 + nt * 8];
                float w00 = expw(c[0], e0.x);
                float w01 = expw(c[1], e0.y);
                float w10 = expw(c[2], e8.x);
                float w11 = expw(c[3], e8.y);
                la += w00 + w01;
                lb += w10 + w11;
                ph0[nt] = pack_bf2(w00, w01);
                ph8[nt] = pack_bf2(w10, w11);
            }
        }

#pragma unroll
        for (int kc = 0; kc < 4; kc++) {
            u32 ah[4] = { ph0[2 * kc], ph8[2 * kc], ph0[2 * kc + 1], ph8[2 * kc + 1] };
            u32 vh[4], vl[4];   // trans: {n0k0-7, n0k8-15, n1k0-7, n1k8-15}
            ldsm4t(vh, sVh_u + kc * 16 * KSTR * 2 + vfoff);
            ldsm4t(vl, sVl_u + kc * 16 * KSTR * 2 + vfoff);
            mma16816(o0, ah, &vh[0]);
            mma16816(o1, ah, &vh[2]);
            mma16816(o0, ah, &vl[0]);
            mma16816(o1, ah, &vl[2]);
        }
    }

    la += __shfl_xor_sync(0xffffffffu, la, 1);
    la += __shfl_xor_sync(0xffffffffu, la, 2);
    lb += __shfl_xor_sync(0xffffffffu, lb, 1);
    lb += __shfl_xor_sync(0xffffffffu, lb, 2);

    float* opa = attp + ((size_t)split * MROWS + grow) * DIM + h * DH;
    float* opb = attp + ((size_t)split * MROWS + grow + 8) * DIM + h * DH;
    *(float2*)&opa[tig * 2]     = make_float2(o0[0], o0[1]);
    *(float2*)&opa[8 + tig * 2] = make_float2(o1[0], o1[1]);
    *(float2*)&opb[tig * 2]     = make_float2(o0[2], o0[3]);
    *(float2*)&opb[8 + tig * 2] = make_float2(o1[2], o1[3]);
    if (tig == 0) {
        lp[((size_t)split * MROWS + grow) * HEADS + h]     = la;
        lp[((size_t)split * MROWS + grow + 8) * HEADS + h] = lb;
    }
}

// ---------------------------------------------------------------------------
// Combine split partials -> normalized att as bf16 hi/lo (1024 blocks).
// ---------------------------------------------------------------------------
__global__ void __launch_bounds__(256) combine_k(
    const float* __restrict__ attp, const float* __restrict__ lp,
    __nv_bfloat16* __restrict__ ath, __nv_bfloat16* __restrict__ atl)
{
    int idx = blockIdx.x * 256 + threadIdx.x;
    int row = idx >> 5;
    int c4  = idx & 31;
    int h   = c4 >> 2;
    float4 s = make_float4(0.f, 0.f, 0.f, 0.f);
    float l = 0.f;
#pragma unroll
    for (int sp = 0; sp < NSPLIT; sp++) {
        float4 vv = *(const float4*)&attp[((size_t)sp * MROWS + row) * DIM + c4 * 4];
        s.x += vv.x; s.y += vv.y; s.z += vv.z; s.w += vv.w;
        l += lp[((size_t)sp * MROWS + row) * HEADS + h];
    }
    float inv = 1.0f / l;
    u32 hp, lp2;
    pack_split2(s.x * inv, s.y * inv, hp, lp2);
    *(u32*)&ath[(size_t)row * DIM + c4 * 4]     = hp;
    *(u32*)&atl[(size_t)row * DIM + c4 * 4]     = lp2;
    pack_split2(s.z * inv, s.w * inv, hp, lp2);
    *(u32*)&ath[(size_t)row * DIM + c4 * 4 + 2] = hp;
    *(u32*)&atl[(size_t)row * DIM + c4 * 4 + 2] = lp2;
}

// ---------------------------------------------------------------------------
// Launch
// ---------------------------------------------------------------------------
extern "C" void kernel_launch(void* const* d_in, const int* in_sizes, int n_in,
                              void* d_out, int out_size)
{
    const float* x  = (const float*)d_in[0];
    const float* e  = (const float*)d_in[1];
    const float* Wq = (const float*)d_in[2];
    const float* Wk = (const float*)d_in[3];
    const float* Wv = (const float*)d_in[4];
    const float* Wo = (const float*)d_in[5];
    const float* W1 = (const float*)d_in[6];
    const float* b1 = (const float*)d_in[7];
    const float* W2 = (const float*)d_in[8];
    const float* b2 = (const float*)d_in[9];
    const float* alpha1 = (const float*)d_in[10];
    const float* alpha2 = (const float*)d_in[11];
    float* out = (float*)d_out;

    float *x1, *attp, *lpv;
    __nv_bfloat16 *qkvh, *qkvl, *xh, *xl, *ath, *atl, *x1h, *x1l, *ffh, *ffl;
    __nv_bfloat16 *WqkvTh, *WqkvTl, *WoTh, *WoTl, *W1Th, *W1Tl, *W2Th, *W2Tl;
    cudaGetSymbolAddress((void**)&x1,   g_x1);
    cudaGetSymbolAddress((void**)&attp, g_attp);
    cudaGetSymbolAddress((void**)&lpv,  g_lp);
    cudaGetSymbolAddress((void**)&qkvh, g_qkvh);
    cudaGetSymbolAddress((void**)&qkvl, g_qkvl);
    cudaGetSymbolAddress((void**)&xh,   g_xh);
    cudaGetSymbolAddress((void**)&xl,   g_xl);
    cudaGetSymbolAddress((void**)&ath,  g_ath);
    cudaGetSymbolAddress((void**)&atl,  g_atl);
    cudaGetSymbolAddress((void**)&x1h,  g_x1h);
    cudaGetSymbolAddress((void**)&x1l,  g_x1l);
    cudaGetSymbolAddress((void**)&ffh,  g_ffh);
    cudaGetSymbolAddress((void**)&ffl,  g_ffl);
    cudaGetSymbolAddress((void**)&WqkvTh, g_WqkvTh);
    cudaGetSymbolAddress((void**)&WqkvTl, g_WqkvTl);
    cudaGetSymbolAddress((void**)&WoTh, g_WoTh);
    cudaGetSymbolAddress((void**)&WoTl, g_WoTl);
    cudaGetSymbolAddress((void**)&W1Th, g_W1Th);
    cudaGetSymbolAddress((void**)&W1Tl, g_W1Tl);
    cudaGetSymbolAddress((void**)&W2Th, g_W2Th);
    cudaGetSymbolAddress((void**)&W2Tl, g_W2Tl);

    // preps (2 launches)
    split_x_k<<<(MROWS * DIM / 4 + 255) / 256, 256>>>(x, xh, xl, MROWS * DIM / 4);
    wsplit_all_k<<<192, 256>>>(Wq, Wk, Wv, Wo, W1, W2,
                               WqkvTh, WqkvTl, WoTh, WoTl,
                               W1Th, W1Tl, W2Th, W2Tl);

    // qkv = x @ [Wq|Wk|Wv] -> bf16 hi/lo (ldcb=384); grid 384 blocks
    mmagemm_k<4><<<dim3(384 / 64, MROWS / 128), 256>>>(
        xh, xl, DIM, WqkvTh, WqkvTl, DIM,
        nullptr, 0, qkvh, qkvl, 384, nullptr, nullptr, 0, nullptr);

    // flash attention with 4-way key splits (2048 blocks)
    attn_mma_k<<<dim3(SEQ / 128, HEADS, BATCH * NSPLIT), 256>>>(qkvh, qkvl, e, attp, lpv);
    combine_k<<<(MROWS * DIM / 4) / 256, 256>>>(attp, lpv, ath, atl);

    // x1 = x + a1*(att @ Wo): 64x64 tiles, grid 256 blocks
    mmagemm64_k<2><<<dim3(DIM / 64, MROWS / 64), 128>>>(
        ath, atl, DIM, WoTh, WoTl, DIM,
        x1, DIM, x1h, x1l, DIM, nullptr, x, DIM, alpha1);

    // ff = relu(x1 @ W1 + b1): grid 512 blocks
    mmagemm_k<1><<<dim3(FFDIM / 64, MROWS / 128), 256>>>(
        x1h, x1l, DIM, W1Th, W1Tl, DIM,
        nullptr, 0, ffh, ffl, FFDIM, b1, nullptr, 0, nullptr);

    // out = x1 + a2*(ff @ W2 + b2): 64x64 tiles, grid 256 blocks
    mmagemm64_k<3><<<dim3(DIM / 64, MROWS / 64), 128>>>(
        ffh, ffl, FFDIM, W2Th, W2Tl, FFDIM,
        out, DIM, nullptr, nullptr, 0, b2, x1, DIM, alpha2);
}